// round 5
// baseline (speedup 1.0000x reference)
#include <cuda_runtime.h>
#include <cstdint>

// ---------------------------------------------------------------------------
// CentralCritic via warp-level tf32 mma.sync (plain sm_103 PTX path).
//   argmax: cidx[i*H+head][b] = argmax_c acs[i,head,b,:]      (tiny kernel)
//   enc:    relu(state[B,256] @ encW[256,128] + b) -> g_enc
//   critic: per pair p (20): h = relu([acs_loo(48)|enc(128)] @ W1 + b1)
//           out = h . W2[:, cidx] + b2[cidx]
// R5: critic = 256 thr / 8 warps, warp tile 32x64 (crossbar traffic -25%),
//     128-reg cap, precomputed argmax, K-half double-buffered cp.async.
// ---------------------------------------------------------------------------

#define A_   4
#define H_   3
#define HI_  2
#define C_   16
#define S_   256
#define D_   128
#define IN_  176
#define NPAIR 20
#define NT    4      // 128-row tiles per critic CTA
#define NTE   4      // 64-row tiles per enc CTA
#define KH    88     // K half
#define KSH   11     // k-steps per half

// smem strides (floats), conflict-free fragment loads
#define XS_ST  92    // X half rows (88+pad): bank = 28g+t, all distinct
#define WS_ST  136   // W rows (128+pad): bank = 8t+g, all distinct
#define XE_ST  260   // enc X rows (256+pad)

// critic smem offsets (floats)
#define WS_OFF   0                       // 176*136 = 23936
#define X0_OFF   23936                   // 128*92  = 11776
#define X1_OFF   35712                   // 128*92  = 11776
#define W2_OFF   47488                   // 128*17  = 2176
#define B1_OFF   49664                   // 128
#define B2_OFF   49792                   // 16
#define PART_OFF 49808                   // 2*128 = 256
#define CIDX_OFF 50064                   // 128
#define K_SMEMB  (50192 * 4)             // 200768 B

// enc smem offsets (floats)
#define WSE_OFF  0                       // 256*136 = 34816
#define XSE_OFF  34816                   // 64*260  = 16640
#define BE_OFF   51456                   // 128
#define E_SMEMB  (51584 * 4)

__device__ float g_enc[32768 * D_];
__device__ int   g_cidx[A_ * H_ * 32768];

__constant__ int c_loo[4][3] = {{1,2,3},{0,2,3},{0,1,3},{0,1,2}};

// ---- helpers ---------------------------------------------------------------
__device__ __forceinline__ uint32_t smem_u32(const void* p) {
    uint32_t r;
    asm("{ .reg .u64 t; cvta.to.shared.u64 t, %1; cvt.u32.u64 %0, t; }"
        : "=r"(r) : "l"(p));
    return r;
}
__device__ __forceinline__ uint32_t tf32r(float x) {
    uint32_t y; asm("cvt.rna.tf32.f32 %0, %1;" : "=r"(y) : "f"(x)); return y;
}
__device__ __forceinline__ void cpasync16(uint32_t dst, const void* src) {
    asm volatile("cp.async.cg.shared.global [%0], [%1], 16;"
                 :: "r"(dst), "l"(src));
}
#define CPCOMMIT()  asm volatile("cp.async.commit_group;" ::: "memory")
#define CPWAITG(n)  asm volatile("cp.async.wait_group %0;" :: "n"(n) : "memory")

__device__ __forceinline__ void mma8(float* d, const uint32_t* a,
                                     const uint32_t* b) {
    asm volatile(
        "mma.sync.aligned.m16n8k8.row.col.f32.tf32.tf32.f32 "
        "{%0,%1,%2,%3}, {%4,%5,%6,%7}, {%8,%9}, {%0,%1,%2,%3};"
        : "+f"(d[0]), "+f"(d[1]), "+f"(d[2]), "+f"(d[3])
        : "r"(a[0]), "r"(a[1]), "r"(a[2]), "r"(a[3]), "r"(b[0]), "r"(b[1]));
}

// ---------------------------------------------------------------------------
// argmax precompute: g_cidx[(i*H+head)*B + b]
// ---------------------------------------------------------------------------
__global__ __launch_bounds__(256) void argmax_kernel(
    const float* __restrict__ acs, int B)
{
    int idx = blockIdx.x * 256 + threadIdx.x;      // over A_*H_*B
    if (idx >= A_ * H_ * B) return;
    const float* ar = acs + (size_t)idx * C_;
    float best = ar[0]; int c = 0;
#pragma unroll
    for (int cc = 1; cc < C_; cc++) {
        float v = ar[cc];
        if (v > best) { best = v; c = cc; }
    }
    g_cidx[idx] = c;
}

// ---------------------------------------------------------------------------
// encoder: [B,256] @ [256,128] + bias, relu -> g_enc.
// ---------------------------------------------------------------------------
__global__ __launch_bounds__(256, 1) void enc_kernel(
    const float* __restrict__ state, const float* __restrict__ encW,
    const float* __restrict__ encb, int B)
{
    extern __shared__ float smf[];
    const int tid = threadIdx.x, wid = tid >> 5, lane = tid & 31;
    const int g = lane >> 2, t = lane & 3;
    const int wm = wid >> 2, wn = wid & 3;
    const int wr = wm * 32, wc = wn * 32;

    for (int it = 0; it < 32; it++) {
        int fi = it * 256 + tid;
        int k = fi >> 5, n4 = fi & 31;
        float4 v = *(const float4*)(encW + (size_t)k * D_ + n4 * 4);
        uint4 w; w.x = tf32r(v.x); w.y = tf32r(v.y);
        w.z = tf32r(v.z); w.w = tf32r(v.w);
        *(uint4*)(smf + WSE_OFF + k * WS_ST + n4 * 4) = w;
    }
    if (tid < D_) smf[BE_OFF + tid] = encb[tid];

    const uint32_t xbase = smem_u32(smf + XSE_OFF);
    const int tile0 = blockIdx.x * NTE;

    {
        int row0 = tile0 * 64;
        for (int it = 0; it < 16; it++) {
            int idx = it * 256 + tid;
            int c = idx & 63, row = idx >> 6;
            cpasync16(xbase + (uint32_t)(row * XE_ST + c * 4) * 4,
                      state + (size_t)(row0 + row) * S_ + c * 4);
        }
        CPCOMMIT();
    }
    CPWAITG(0);
    __syncthreads();

    for (int tt = 0; tt < NTE; tt++) {
        const int row0 = (tile0 + tt) * 64;
        float acc[2][4][4];
#pragma unroll
        for (int mi = 0; mi < 2; mi++)
#pragma unroll
            for (int ni = 0; ni < 4; ni++)
#pragma unroll
                for (int e = 0; e < 4; e++) acc[mi][ni][e] = 0.f;

        const uint32_t* Xu = (const uint32_t*)(smf + XSE_OFF);
        const uint32_t* Wu = (const uint32_t*)(smf + WSE_OFF);
#pragma unroll
        for (int ks = 0; ks < 32; ks++) {
            const int k0 = ks * 8;
            uint32_t a[2][4], b[4][2];
#pragma unroll
            for (int mi = 0; mi < 2; mi++) {
                int r = wr + mi * 16 + g;
                a[mi][0] = Xu[r * XE_ST + k0 + t];
                a[mi][1] = Xu[(r + 8) * XE_ST + k0 + t];
                a[mi][2] = Xu[r * XE_ST + k0 + t + 4];
                a[mi][3] = Xu[(r + 8) * XE_ST + k0 + t + 4];
            }
#pragma unroll
            for (int ni = 0; ni < 4; ni++) {
                int n = wc + ni * 8 + g;
                b[ni][0] = Wu[(k0 + t) * WS_ST + n];
                b[ni][1] = Wu[(k0 + t + 4) * WS_ST + n];
            }
#pragma unroll
            for (int mi = 0; mi < 2; mi++)
#pragma unroll
                for (int ni = 0; ni < 4; ni++)
                    mma8(acc[mi][ni], a[mi], b[ni]);
        }
        __syncthreads();

        if (tt + 1 < NTE) {
            int nrow0 = (tile0 + tt + 1) * 64;
            for (int it = 0; it < 16; it++) {
                int idx = it * 256 + tid;
                int c = idx & 63, row = idx >> 6;
                cpasync16(xbase + (uint32_t)(row * XE_ST + c * 4) * 4,
                          state + (size_t)(nrow0 + row) * S_ + c * 4);
            }
            CPCOMMIT();
        }

#pragma unroll
        for (int mi = 0; mi < 2; mi++) {
            int r0 = row0 + wr + mi * 16 + g;
#pragma unroll
            for (int ni = 0; ni < 4; ni++) {
                int col = wc + ni * 8 + 2 * t;
                float b0 = smf[BE_OFF + col], b1v = smf[BE_OFF + col + 1];
                float2 o0, o1;
                o0.x = fmaxf(acc[mi][ni][0] + b0, 0.f);
                o0.y = fmaxf(acc[mi][ni][1] + b1v, 0.f);
                o1.x = fmaxf(acc[mi][ni][2] + b0, 0.f);
                o1.y = fmaxf(acc[mi][ni][3] + b1v, 0.f);
                *(float2*)(g_enc + (size_t)r0 * D_ + col) = o0;
                *(float2*)(g_enc + (size_t)(r0 + 8) * D_ + col) = o1;
            }
        }

        if (tt + 1 < NTE) CPWAITG(0);
        __syncthreads();
    }
}

// ---------------------------------------------------------------------------
// critic: 256 thr, 8 warps (4 wm x 2 wn), warp tile 32x64, 128-reg cap,
// K-half double buffering, precomputed argmax indices.
// ---------------------------------------------------------------------------
__global__ __launch_bounds__(256, 2) void critic_kernel(
    const float* __restrict__ acs,
    const float* __restrict__ eW1, const float* __restrict__ eb1,
    const float* __restrict__ eW2, const float* __restrict__ eb2,
    const float* __restrict__ iW1, const float* __restrict__ ib1,
    const float* __restrict__ iW2, const float* __restrict__ ib2,
    float* __restrict__ out, int B)
{
    extern __shared__ float smf[];
    const int tid = threadIdx.x, wid = tid >> 5, lane = tid & 31;
    const int g = lane >> 2, t = lane & 3;
    const int wm = wid >> 1, wn = wid & 1;
    const int wr = wm * 32, wc = wn * 64;
    const int p = blockIdx.y;

    int i, head;
    const float *W1, *b1, *W2, *b2;
    float* outp;
    if (p < A_ * H_) {
        i = p / H_; int j = p % H_; head = j;
        W1 = eW1 + (size_t)(j * A_ + i) * IN_ * D_;
        b1 = eb1 + (size_t)(j * A_ + i) * D_;
        W2 = eW2 + (size_t)(j * A_ + i) * D_ * C_;
        b2 = eb2 + (size_t)(j * A_ + i) * C_;
        outp = out + (size_t)p * B;
    } else {
        int q = p - A_ * H_;
        i = q / HI_; int j = q % HI_; head = j + 1;
        W1 = iW1 + (size_t)(j * A_ + i) * IN_ * D_;
        b1 = ib1 + (size_t)(j * A_ + i) * D_;
        W2 = iW2 + (size_t)(j * A_ + i) * D_ * C_;
        b2 = ib2 + (size_t)(j * A_ + i) * C_;
        outp = out + (size_t)(A_ * H_) * B + (size_t)q * B;
    }
    const float* acsA[3];
    acsA[0] = acs + (size_t)(c_loo[i][0] * H_ + head) * B * C_;
    acsA[1] = acs + (size_t)(c_loo[i][1] * H_ + head) * B * C_;
    acsA[2] = acs + (size_t)(c_loo[i][2] * H_ + head) * B * C_;
    const int* cidxg = g_cidx + (size_t)(i * H_ + head) * B;

    // ---- stage W1 (cvt.rna), W2 (stride 17), b1, b2 ----
    for (int it = 0; it < 22; it++) {
        int fi = it * 256 + tid;            // 5632 float4
        int k = fi >> 5, n4 = fi & 31;
        float4 v = *(const float4*)(W1 + (size_t)k * D_ + n4 * 4);
        uint4 w; w.x = tf32r(v.x); w.y = tf32r(v.y);
        w.z = tf32r(v.z); w.w = tf32r(v.w);
        *(uint4*)(smf + WS_OFF + k * WS_ST + n4 * 4) = w;
    }
    for (int it = 0; it < 8; it++) {
        int idx = it * 256 + tid;           // 2048 floats
        int d = idx >> 4, c = idx & 15;
        smf[W2_OFF + d * 17 + c] = W2[idx];
    }
    if (tid < D_) smf[B1_OFF + tid] = b1[tid];
    if (tid < C_) smf[B2_OFF + tid] = b2[tid];

    const uint32_t x0b = smem_u32(smf + X0_OFF);
    const uint32_t x1b = smem_u32(smf + X1_OFF);
    const int tile0 = blockIdx.x * NT;
    int* cidx = (int*)(smf + CIDX_OFF);

    auto stage_half0 = [&](int row0) {
#pragma unroll
        for (int it = 0; it < 11; it++) {
            int idx = it * 256 + tid;       // 2816 chunks
            int row = idx / 22, c = idx - row * 22;
            const void* src;
            if (c < 12)
                src = acsA[c >> 2] + (size_t)(row0 + row) * C_ + (c & 3) * 4;
            else
                src = g_enc + (size_t)(row0 + row) * D_ + (c - 12) * 4;
            cpasync16(x0b + (uint32_t)(row * XS_ST + c * 4) * 4, src);
        }
        CPCOMMIT();
    };
    auto stage_half1 = [&](int row0) {
#pragma unroll
        for (int it = 0; it < 11; it++) {
            int idx = it * 256 + tid;
            int row = idx / 22, c = idx - row * 22;
            const void* src = g_enc + (size_t)(row0 + row) * D_ + 40 + c * 4;
            cpasync16(x1b + (uint32_t)(row * XS_ST + c * 4) * 4, src);
        }
        CPCOMMIT();
    };

    // prologue
    stage_half0(tile0 * 128);
    stage_half1(tile0 * 128);

    for (int tt = 0; tt < NT; tt++) {
        const int row0 = (tile0 + tt) * 128;
        float acc[2][8][4];
#pragma unroll
        for (int mi = 0; mi < 2; mi++)
#pragma unroll
            for (int ni = 0; ni < 8; ni++)
#pragma unroll
                for (int e = 0; e < 4; e++) acc[mi][ni][e] = 0.f;

        const uint32_t* Wu = (const uint32_t*)(smf + WS_OFF);

        // ---- half 0 ----
        CPWAITG(1);            // S(tt,0) complete
        __syncthreads();
        if (tid < 128) cidx[tid] = cidxg[row0 + tid];   // prefetch indices
        {
            const uint32_t* Xu = (const uint32_t*)(smf + X0_OFF);
#pragma unroll
            for (int ks = 0; ks < KSH; ks++) {
                const int k0 = ks * 8;
                uint32_t a[2][4], b[8][2];
#pragma unroll
                for (int mi = 0; mi < 2; mi++) {
                    int r = wr + mi * 16 + g;
                    a[mi][0] = Xu[r * XS_ST + k0 + t];
                    a[mi][1] = Xu[(r + 8) * XS_ST + k0 + t];
                    a[mi][2] = Xu[r * XS_ST + k0 + t + 4];
                    a[mi][3] = Xu[(r + 8) * XS_ST + k0 + t + 4];
                }
#pragma unroll
                for (int ni = 0; ni < 8; ni++) {
                    int n = wc + ni * 8 + g;
                    b[ni][0] = Wu[(k0 + t) * WS_ST + n];
                    b[ni][1] = Wu[(k0 + t + 4) * WS_ST + n];
                }
#pragma unroll
                for (int mi = 0; mi < 2; mi++)
#pragma unroll
                    for (int ni = 0; ni < 8; ni++)
                        mma8(acc[mi][ni], a[mi], b[ni]);
            }
        }
        __syncthreads();       // buf0 consumed
        if (tt + 1 < NT) stage_half0((tile0 + tt + 1) * 128);

        // ---- half 1 ----
        if (tt + 1 < NT) { CPWAITG(1); } else { CPWAITG(0); }
        __syncthreads();
        {
            const uint32_t* Xu = (const uint32_t*)(smf + X1_OFF);
#pragma unroll
            for (int ks = 0; ks < KSH; ks++) {
                const int k0 = ks * 8;
                const int kw = KH + k0;
                uint32_t a[2][4], b[8][2];
#pragma unroll
                for (int mi = 0; mi < 2; mi++) {
                    int r = wr + mi * 16 + g;
                    a[mi][0] = Xu[r * XS_ST + k0 + t];
                    a[mi][1] = Xu[(r + 8) * XS_ST + k0 + t];
                    a[mi][2] = Xu[r * XS_ST + k0 + t + 4];
                    a[mi][3] = Xu[(r + 8) * XS_ST + k0 + t + 4];
                }
#pragma unroll
                for (int ni = 0; ni < 8; ni++) {
                    int n = wc + ni * 8 + g;
                    b[ni][0] = Wu[(kw + t) * WS_ST + n];
                    b[ni][1] = Wu[(kw + t + 4) * WS_ST + n];
                }
#pragma unroll
                for (int mi = 0; mi < 2; mi++)
#pragma unroll
                    for (int ni = 0; ni < 8; ni++)
                        mma8(acc[mi][ni], a[mi], b[ni]);
            }
        }
        __syncthreads();       // buf1 consumed + cidx visible
        if (tt + 1 < NT) stage_half1((tile0 + tt + 1) * 128);

        // ---- epilogue: relu(acc+b1) . W2[:,c], 2-way N reduction ----
#pragma unroll
        for (int mi = 0; mi < 2; mi++) {
            int r0 = wr + mi * 16 + g;
            int cR0 = cidx[r0], cR1 = cidx[r0 + 8];
            float s0 = 0.f, s1 = 0.f;
#pragma unroll
            for (int ni = 0; ni < 8; ni++) {
                int col0 = wc + ni * 8 + 2 * t;
                float bb0 = smf[B1_OFF + col0], bb1 = smf[B1_OFF + col0 + 1];
                float w00 = smf[W2_OFF + col0 * 17 + cR0];
                float w01 = smf[W2_OFF + (col0 + 1) * 17 + cR0];
                float w10 = smf[W2_OFF + col0 * 17 + cR1];
                float w11 = smf[W2_OFF + (col0 + 1) * 17 + cR1];
                s0 += fmaxf(acc[mi][ni][0] + bb0, 0.f) * w00
                    + fmaxf(acc[mi][ni][1] + bb1, 0.f) * w01;
                s1 += fmaxf(acc[mi][ni][2] + bb0, 0.f) * w10
                    + fmaxf(acc[mi][ni][3] + bb1, 0.f) * w11;
            }
            s0 += __shfl_xor_sync(0xffffffffu, s0, 1);
            s0 += __shfl_xor_sync(0xffffffffu, s0, 2);
            s1 += __shfl_xor_sync(0xffffffffu, s1, 1);
            s1 += __shfl_xor_sync(0xffffffffu, s1, 2);
            if (t == 0) {
                smf[PART_OFF + wn * 128 + r0] = s0;
                smf[PART_OFF + wn * 128 + r0 + 8] = s1;
            }
        }
        __syncthreads();
        if (tid < 128) {
            float q = smf[PART_OFF + tid] + smf[PART_OFF + 128 + tid]
                    + smf[B2_OFF + cidx[tid]];
            outp[row0 + tid] = q;
        }
        __syncthreads();       // PART/cidx reusable next tile
    }
}

// ---------------------------------------------------------------------------
extern "C" void kernel_launch(void* const* d_in, const int* in_sizes, int n_in,
                              void* d_out, int out_size)
{
    const float* state = (const float*)d_in[0];
    const float* acs   = (const float*)d_in[1];
    const float* encW  = (const float*)d_in[2];
    const float* encb  = (const float*)d_in[3];
    const float* eW1   = (const float*)d_in[4];
    const float* eb1   = (const float*)d_in[5];
    const float* eW2   = (const float*)d_in[6];
    const float* eb2   = (const float*)d_in[7];
    const float* iW1   = (const float*)d_in[8];
    const float* ib1   = (const float*)d_in[9];
    const float* iW2   = (const float*)d_in[10];
    const float* ib2   = (const float*)d_in[11];
    float* out = (float*)d_out;

    const int B = in_sizes[0] / S_;          // 32768

    cudaFuncSetAttribute(enc_kernel,
        cudaFuncAttributeMaxDynamicSharedMemorySize, E_SMEMB);
    cudaFuncSetAttribute(critic_kernel,
        cudaFuncAttributeMaxDynamicSharedMemorySize, K_SMEMB);

    argmax_kernel<<<(A_ * H_ * B + 255) / 256, 256>>>(acs, B);
    enc_kernel<<<B / 64 / NTE, 256, E_SMEMB>>>(state, encW, encb, B);

    dim3 grid(B / 128 / NT, NPAIR);
    critic_kernel<<<grid, 256, K_SMEMB>>>(acs, eW1, eb1, eW2, eb2,
                                          iW1, ib1, iW2, ib2, out, B);
}

// round 6
// speedup vs baseline: 1.1248x; 1.1248x over previous
#include <cuda_runtime.h>
#include <cstdint>

// ---------------------------------------------------------------------------
// CentralCritic via warp-level tf32 mma.sync (plain sm_103 PTX path).
// R6: pair-packed W (LDS.64 b-frags) + pair-packed g_enc (LDS.64 a-frags for
//     enc region) -> MMA-loop LDS instr count -45% at constant bytes.
//     NT=8, inline argmax, no reg cap (R3-style 32x64 warp tiles, 8 warps).
// ---------------------------------------------------------------------------

#define A_   4
#define H_   3
#define HI_  2
#define C_   16
#define S_   256
#define D_   128
#define IN_  176
#define NPAIR 20
#define NT    8      // 128-row tiles per critic CTA
#define NTE   4      // 64-row tiles per enc CTA

// enc kernel strides
#define WS_ST  136   // enc W rows (128+pad) floats
#define XE_ST  260   // enc X rows (256+pad) floats

// critic smem layout (float offsets)
#define WP_OFF   0                       // 88*132 f2 = 23232 floats
#define X0A_OFF  23232                   // 128*52 = 6656
#define X0E_OFF  29888                   // 128*20 f2 = 5120
#define X1_OFF   35008                   // 128*52 f2 = 13312
#define W2_OFF   48320                   // 128*17 = 2176
#define B1_OFF   50496                   // 128
#define B2_OFF   50624                   // 16
#define PART_OFF 50640                   // 256
#define CIDX_OFF 50896                   // 128
#define K_SMEMB  (51024 * 4)             // 204096 B

// enc smem offsets (floats)
#define WSE_OFF  0                       // 256*136 = 34816
#define XSE_OFF  34816                   // 64*260  = 16640
#define BE_OFF   51456                   // 128
#define E_SMEMB  (51584 * 4)

__device__ float g_encp[32768 * D_];     // pair-packed enc activations

__constant__ int c_loo[4][3] = {{1,2,3},{0,2,3},{0,1,3},{0,1,2}};

// ---- helpers ---------------------------------------------------------------
__device__ __forceinline__ uint32_t smem_u32(const void* p) {
    uint32_t r;
    asm("{ .reg .u64 t; cvta.to.shared.u64 t, %1; cvt.u32.u64 %0, t; }"
        : "=r"(r) : "l"(p));
    return r;
}
__device__ __forceinline__ uint32_t tf32r(float x) {
    uint32_t y; asm("cvt.rna.tf32.f32 %0, %1;" : "=r"(y) : "f"(x)); return y;
}
__device__ __forceinline__ void cpasync16(uint32_t dst, const void* src) {
    asm volatile("cp.async.cg.shared.global [%0], [%1], 16;"
                 :: "r"(dst), "l"(src));
}
#define CPCOMMIT()  asm volatile("cp.async.commit_group;" ::: "memory")
#define CPWAITG(n)  asm volatile("cp.async.wait_group %0;" :: "n"(n) : "memory")

__device__ __forceinline__ void mma8(float* d, const uint32_t* a,
                                     const uint32_t* b) {
    asm volatile(
        "mma.sync.aligned.m16n8k8.row.col.f32.tf32.tf32.f32 "
        "{%0,%1,%2,%3}, {%4,%5,%6,%7}, {%8,%9}, {%0,%1,%2,%3};"
        : "+f"(d[0]), "+f"(d[1]), "+f"(d[2]), "+f"(d[3])
        : "r"(a[0]), "r"(a[1]), "r"(a[2]), "r"(a[3]), "r"(b[0]), "r"(b[1]));
}

// pair-pack index within a row: col d -> float position
__device__ __forceinline__ int pidx(int d) {
    return (d >> 3) * 8 + (d & 3) * 2 + ((d >> 2) & 1);
}

// ---------------------------------------------------------------------------
// encoder: relu(state @ encW + b) -> g_encp (pair-packed rows of 128).
// ---------------------------------------------------------------------------
__global__ __launch_bounds__(256, 1) void enc_kernel(
    const float* __restrict__ state, const float* __restrict__ encW,
    const float* __restrict__ encb, int B)
{
    extern __shared__ float smf[];
    const int tid = threadIdx.x, wid = tid >> 5, lane = tid & 31;
    const int g = lane >> 2, t = lane & 3;
    const int wm = wid >> 2, wn = wid & 3;
    const int wr = wm * 32, wc = wn * 32;

    for (int it = 0; it < 32; it++) {
        int fi = it * 256 + tid;
        int k = fi >> 5, n4 = fi & 31;
        float4 v = *(const float4*)(encW + (size_t)k * D_ + n4 * 4);
        uint4 w; w.x = tf32r(v.x); w.y = tf32r(v.y);
        w.z = tf32r(v.z); w.w = tf32r(v.w);
        *(uint4*)(smf + WSE_OFF + k * WS_ST + n4 * 4) = w;
    }
    if (tid < D_) smf[BE_OFF + tid] = encb[tid];

    const uint32_t xbase = smem_u32(smf + XSE_OFF);
    const int tile0 = blockIdx.x * NTE;

    {
        int row0 = tile0 * 64;
        for (int it = 0; it < 16; it++) {
            int idx = it * 256 + tid;
            int c = idx & 63, row = idx >> 6;
            cpasync16(xbase + (uint32_t)(row * XE_ST + c * 4) * 4,
                      state + (size_t)(row0 + row) * S_ + c * 4);
        }
        CPCOMMIT();
    }
    CPWAITG(0);
    __syncthreads();

    for (int tt = 0; tt < NTE; tt++) {
        const int row0 = (tile0 + tt) * 64;
        float acc[2][4][4];
#pragma unroll
        for (int mi = 0; mi < 2; mi++)
#pragma unroll
            for (int ni = 0; ni < 4; ni++)
#pragma unroll
                for (int e = 0; e < 4; e++) acc[mi][ni][e] = 0.f;

        const uint32_t* Xu = (const uint32_t*)(smf + XSE_OFF);
        const uint32_t* Wu = (const uint32_t*)(smf + WSE_OFF);
#pragma unroll
        for (int ks = 0; ks < 32; ks++) {
            const int k0 = ks * 8;
            uint32_t a[2][4], b[4][2];
#pragma unroll
            for (int mi = 0; mi < 2; mi++) {
                int r = wr + mi * 16 + g;
                a[mi][0] = Xu[r * XE_ST + k0 + t];
                a[mi][1] = Xu[(r + 8) * XE_ST + k0 + t];
                a[mi][2] = Xu[r * XE_ST + k0 + t + 4];
                a[mi][3] = Xu[(r + 8) * XE_ST + k0 + t + 4];
            }
#pragma unroll
            for (int ni = 0; ni < 4; ni++) {
                int n = wc + ni * 8 + g;
                b[ni][0] = Wu[(k0 + t) * WS_ST + n];
                b[ni][1] = Wu[(k0 + t + 4) * WS_ST + n];
            }
#pragma unroll
            for (int mi = 0; mi < 2; mi++)
#pragma unroll
                for (int ni = 0; ni < 4; ni++)
                    mma8(acc[mi][ni], a[mi], b[ni]);
        }
        __syncthreads();

        if (tt + 1 < NTE) {
            int nrow0 = (tile0 + tt + 1) * 64;
            for (int it = 0; it < 16; it++) {
                int idx = it * 256 + tid;
                int c = idx & 63, row = idx >> 6;
                cpasync16(xbase + (uint32_t)(row * XE_ST + c * 4) * 4,
                          state + (size_t)(nrow0 + row) * S_ + c * 4);
            }
            CPCOMMIT();
        }

        // epilogue: bias + relu, scatter-store into pair-packed g_encp
#pragma unroll
        for (int mi = 0; mi < 2; mi++) {
            int r0 = row0 + wr + mi * 16 + g;
#pragma unroll
            for (int ni = 0; ni < 4; ni++) {
                int col = wc + ni * 8 + 2 * t;
                float b0 = smf[BE_OFF + col], b1v = smf[BE_OFF + col + 1];
                g_encp[(size_t)r0 * D_ + pidx(col)] =
                    fmaxf(acc[mi][ni][0] + b0, 0.f);
                g_encp[(size_t)r0 * D_ + pidx(col + 1)] =
                    fmaxf(acc[mi][ni][1] + b1v, 0.f);
                g_encp[(size_t)(r0 + 8) * D_ + pidx(col)] =
                    fmaxf(acc[mi][ni][2] + b0, 0.f);
                g_encp[(size_t)(r0 + 8) * D_ + pidx(col + 1)] =
                    fmaxf(acc[mi][ni][3] + b1v, 0.f);
            }
        }

        if (tt + 1 < NTE) CPWAITG(0);
        __syncthreads();
    }
}

// ---------------------------------------------------------------------------
// critic: 256 thr, 8 warps (4 wm x 2 wn), warp tile 32x64,
// pair-packed W + enc-X for LDS.64 fragment feeds.
// ---------------------------------------------------------------------------
__global__ __launch_bounds__(256, 1) void critic_kernel(
    const float* __restrict__ acs,
    const float* __restrict__ eW1, const float* __restrict__ eb1,
    const float* __restrict__ eW2, const float* __restrict__ eb2,
    const float* __restrict__ iW1, const float* __restrict__ ib1,
    const float* __restrict__ iW2, const float* __restrict__ ib2,
    float* __restrict__ out, int B)
{
    extern __shared__ float smf[];
    const int tid = threadIdx.x, wid = tid >> 5, lane = tid & 31;
    const int g = lane >> 2, t = lane & 3;
    const int wm = wid >> 1, wn = wid & 1;
    const int wr = wm * 32, wc = wn * 64;
    const int p = blockIdx.y;

    int i, head;
    const float *W1, *b1, *W2, *b2;
    float* outp;
    if (p < A_ * H_) {
        i = p / H_; int j = p % H_; head = j;
        W1 = eW1 + (size_t)(j * A_ + i) * IN_ * D_;
        b1 = eb1 + (size_t)(j * A_ + i) * D_;
        W2 = eW2 + (size_t)(j * A_ + i) * D_ * C_;
        b2 = eb2 + (size_t)(j * A_ + i) * C_;
        outp = out + (size_t)p * B;
    } else {
        int q = p - A_ * H_;
        i = q / HI_; int j = q % HI_; head = j + 1;
        W1 = iW1 + (size_t)(j * A_ + i) * IN_ * D_;
        b1 = ib1 + (size_t)(j * A_ + i) * D_;
        W2 = iW2 + (size_t)(j * A_ + i) * D_ * C_;
        b2 = ib2 + (size_t)(j * A_ + i) * C_;
        outp = out + (size_t)(A_ * H_) * B + (size_t)q * B;
    }
    const float* acsA[3];
    acsA[0] = acs + (size_t)(c_loo[i][0] * H_ + head) * B * C_;
    acsA[1] = acs + (size_t)(c_loo[i][1] * H_ + head) * B * C_;
    acsA[2] = acs + (size_t)(c_loo[i][2] * H_ + head) * B * C_;
    const float* acsSelf = acs + (size_t)(i * H_ + head) * B * C_;

    // ---- stage W1 pair-packed (cvt.rna), W2 (stride 17), b1, b2 ----
    // Wp[kp][n] f2 stride 132: kp = (k>>3)*4 + (k&3), comp = (k>>2)&1
    for (int it = 0; it < 22; it++) {
        int fi = it * 256 + tid;            // 5632 float4
        int k = fi >> 5, n0 = (fi & 31) * 4;
        float4 v = *(const float4*)(W1 + (size_t)k * D_ + n0);
        int kp = (k >> 3) * 4 + (k & 3);
        int comp = (k >> 2) & 1;
        int base = (kp * 132) * 2 + comp;   // float index into Wp
        smf[WP_OFF + base + (n0 + 0) * 2] = __uint_as_float(tf32r(v.x));
        smf[WP_OFF + base + (n0 + 1) * 2] = __uint_as_float(tf32r(v.y));
        smf[WP_OFF + base + (n0 + 2) * 2] = __uint_as_float(tf32r(v.z));
        smf[WP_OFF + base + (n0 + 3) * 2] = __uint_as_float(tf32r(v.w));
    }
    for (int it = 0; it < 8; it++) {
        int idx = it * 256 + tid;           // 2048 floats
        int d = idx >> 4, c = idx & 15;
        smf[W2_OFF + d * 17 + c] = W2[idx];
    }
    if (tid < D_) smf[B1_OFF + tid] = b1[tid];
    if (tid < C_) smf[B2_OFF + tid] = b2[tid];

    const uint32_t x0ab = smem_u32(smf + X0A_OFF);
    const uint32_t x0eb = smem_u32(smf + X0E_OFF);
    const uint32_t x1b  = smem_u32(smf + X1_OFF);
    const int tile0 = blockIdx.x * NT;
    int* cidx = (int*)(smf + CIDX_OFF);

    // buf0: acs plain (12 chunks/row) + enc pairs f2-cols 0..19 (10 chunks/row)
    auto stage_buf0 = [&](int row0) {
#pragma unroll
        for (int it = 0; it < 11; it++) {
            int idx = it * 256 + tid;       // 2816 chunks
            int row = idx / 22, c = idx - (idx / 22) * 22;
            if (c < 12) {
                const void* src =
                    acsA[c >> 2] + (size_t)(row0 + row) * C_ + (c & 3) * 4;
                cpasync16(x0ab + (uint32_t)(row * 52 + c * 4) * 4, src);
            } else {
                int u = c - 12;
                const void* src =
                    g_encp + (size_t)(row0 + row) * D_ + u * 4;
                cpasync16(x0eb + (uint32_t)(row * 40 + u * 4) * 4, src);
            }
        }
        CPCOMMIT();
    };
    // buf1: enc pairs f2-cols 20..63 (22 chunks/row)
    auto stage_buf1 = [&](int row0) {
#pragma unroll
        for (int it = 0; it < 11; it++) {
            int idx = it * 256 + tid;
            int row = idx / 22, u = idx - (idx / 22) * 22;
            const void* src =
                g_encp + (size_t)(row0 + row) * D_ + 40 + u * 4;
            cpasync16(x1b + (uint32_t)(row * 104 + u * 4) * 4, src);
        }
        CPCOMMIT();
    };

    stage_buf0(tile0 * 128);
    stage_buf1(tile0 * 128);

    const uint32_t* Xa  = (const uint32_t*)(smf + X0A_OFF);
    const uint2*    Xe0 = (const uint2*)(smf + X0E_OFF);
    const uint2*    Xe1 = (const uint2*)(smf + X1_OFF);
    const uint2*    Wp  = (const uint2*)(smf + WP_OFF);

    for (int tt = 0; tt < NT; tt++) {
        const int row0 = (tile0 + tt) * 128;
        float acc[2][8][4];
#pragma unroll
        for (int mi = 0; mi < 2; mi++)
#pragma unroll
            for (int ni = 0; ni < 8; ni++)
#pragma unroll
                for (int e = 0; e < 4; e++) acc[mi][ni][e] = 0.f;

        // ---- half 0: ks 0..10 ----
        CPWAITG(1);
        __syncthreads();
#pragma unroll
        for (int ks = 0; ks < 6; ks++) {       // acs region, LDS.32
            const int k0 = ks * 8;
            uint32_t a[2][4], b[8][2];
#pragma unroll
            for (int mi = 0; mi < 2; mi++) {
                int r = wr + mi * 16 + g;
                a[mi][0] = Xa[r * 52 + k0 + t];
                a[mi][1] = Xa[(r + 8) * 52 + k0 + t];
                a[mi][2] = Xa[r * 52 + k0 + t + 4];
                a[mi][3] = Xa[(r + 8) * 52 + k0 + t + 4];
            }
#pragma unroll
            for (int ni = 0; ni < 8; ni++) {
                int n = wc + ni * 8 + g;
                uint2 bv = Wp[(ks * 4 + t) * 132 + n];
                b[ni][0] = bv.x; b[ni][1] = bv.y;
            }
#pragma unroll
            for (int mi = 0; mi < 2; mi++)
#pragma unroll
                for (int ni = 0; ni < 8; ni++)
                    mma8(acc[mi][ni], a[mi], b[ni]);
        }
#pragma unroll
        for (int ks = 6; ks < 11; ks++) {      // enc pairs, LDS.64
            uint32_t a[2][4], b[8][2];
#pragma unroll
            for (int mi = 0; mi < 2; mi++) {
                int r = wr + mi * 16 + g;
                uint2 A0 = Xe0[r * 20 + (ks - 6) * 4 + t];
                uint2 A1 = Xe0[(r + 8) * 20 + (ks - 6) * 4 + t];
                a[mi][0] = A0.x; a[mi][1] = A1.x;
                a[mi][2] = A0.y; a[mi][3] = A1.y;
            }
#pragma unroll
            for (int ni = 0; ni < 8; ni++) {
                int n = wc + ni * 8 + g;
                uint2 bv = Wp[(ks * 4 + t) * 132 + n];
                b[ni][0] = bv.x; b[ni][1] = bv.y;
            }
#pragma unroll
            for (int mi = 0; mi < 2; mi++)
#pragma unroll
                for (int ni = 0; ni < 8; ni++)
                    mma8(acc[mi][ni], a[mi], b[ni]);
        }
        __syncthreads();
        if (tt + 1 < NT) stage_buf0((tile0 + tt + 1) * 128);

        // argmax (overlaps cp.async flight + half1 wait)
        if (tid < 128) {
            const float* ar = acsSelf + (size_t)(row0 + tid) * C_;
            float4 v0 = *(const float4*)ar;
            float4 v1 = *(const float4*)(ar + 4);
            float4 v2 = *(const float4*)(ar + 8);
            float4 v3 = *(const float4*)(ar + 12);
            float vv[16] = {v0.x,v0.y,v0.z,v0.w, v1.x,v1.y,v1.z,v1.w,
                            v2.x,v2.y,v2.z,v2.w, v3.x,v3.y,v3.z,v3.w};
            float best = vv[0]; int c = 0;
#pragma unroll
            for (int cc = 1; cc < C_; cc++)
                if (vv[cc] > best) { best = vv[cc]; c = cc; }
            cidx[tid] = c;
        }

        // ---- half 1: ks 11..21 ----
        if (tt + 1 < NT) { CPWAITG(1); } else { CPWAITG(0); }
        __syncthreads();
#pragma unroll
        for (int ks = 11; ks < 22; ks++) {
            uint32_t a[2][4], b[8][2];
#pragma unroll
            for (int mi = 0; mi < 2; mi++) {
                int r = wr + mi * 16 + g;
                uint2 A0 = Xe1[r * 52 + (ks - 11) * 4 + t];
                uint2 A1 = Xe1[(r + 8) * 52 + (ks - 11) * 4 + t];
                a[mi][0] = A0.x; a[mi][1] = A1.x;
                a[mi][2] = A0.y; a[mi][3] = A1.y;
            }
#pragma unroll
            for (int ni = 0; ni < 8; ni++) {
                int n = wc + ni * 8 + g;
                uint2 bv = Wp[(ks * 4 + t) * 132 + n];
                b[ni][0] = bv.x; b[ni][1] = bv.y;
            }
#pragma unroll
            for (int mi = 0; mi < 2; mi++)
#pragma unroll
                for (int ni = 0; ni < 8; ni++)
                    mma8(acc[mi][ni], a[mi], b[ni]);
        }
        __syncthreads();       // buf1 consumed + cidx visible
        if (tt + 1 < NT) stage_buf1((tile0 + tt + 1) * 128);

        // ---- epilogue: relu(acc+b1) . W2[:,c], 2-way N reduction ----
#pragma unroll
        for (int mi = 0; mi < 2; mi++) {
            int r0 = wr + mi * 16 + g;
            int cR0 = cidx[r0], cR1 = cidx[r0 + 8];
            float s0 = 0.f, s1 = 0.f;
#pragma unroll
            for (int ni = 0; ni < 8; ni++) {
                int col0 = wc + ni * 8 + 2 * t;
                float bb0 = smf[B1_OFF + col0], bb1 = smf[B1_OFF + col0 + 1];
                float w00 = smf[W2_OFF + col0 * 17 + cR0];
                float w01 = smf[W2_OFF + (col0 + 1) * 17 + cR0];
                float w10 = smf[W2_OFF + col0 * 17 + cR1];
                float w11 = smf[W2_OFF + (col0 + 1) * 17 + cR1];
                s0 += fmaxf(acc[mi][ni][0] + bb0, 0.f) * w00
                    + fmaxf(acc[mi][ni][1] + bb1, 0.f) * w01;
                s1 += fmaxf(acc[mi][ni][2] + bb0, 0.f) * w10
                    + fmaxf(acc[mi][ni][3] + bb1, 0.f) * w11;
            }
            s0 += __shfl_xor_sync(0xffffffffu, s0, 1);
            s0 += __shfl_xor_sync(0xffffffffu, s0, 2);
            s1 += __shfl_xor_sync(0xffffffffu, s1, 1);
            s1 += __shfl_xor_sync(0xffffffffu, s1, 2);
            if (t == 0) {
                smf[PART_OFF + wn * 128 + r0] = s0;
                smf[PART_OFF + wn * 128 + r0 + 8] = s1;
            }
        }
        __syncthreads();
        if (tid < 128) {
            float q = smf[PART_OFF + tid] + smf[PART_OFF + 128 + tid]
                    + smf[B2_OFF + cidx[tid]];
            outp[row0 + tid] = q;
        }
        __syncthreads();
    }
}

// ---------------------------------------------------------------------------
extern "C" void kernel_launch(void* const* d_in, const int* in_sizes, int n_in,
                              void* d_out, int out_size)
{
    const float* state = (const float*)d_in[0];
    const float* acs   = (const float*)d_in[1];
    const float* encW  = (const float*)d_in[2];
    const float* encb  = (const float*)d_in[3];
    const float* eW1   = (const float*)d_in[4];
    const float* eb1   = (const float*)d_in[5];
    const float* eW2   = (const float*)d_in[6];
    const float* eb2   = (const float*)d_in[7];
    const float* iW1   = (const float*)d_in[8];
    const float* ib1   = (const float*)d_in[9];
    const float* iW2   = (const float*)d_in[10];
    const float* ib2   = (const float*)d_in[11];
    float* out = (float*)d_out;

    const int B = in_sizes[0] / S_;          // 32768

    cudaFuncSetAttribute(enc_kernel,
        cudaFuncAttributeMaxDynamicSharedMemorySize, E_SMEMB);
    cudaFuncSetAttribute(critic_kernel,
        cudaFuncAttributeMaxDynamicSharedMemorySize, K_SMEMB);

    enc_kernel<<<B / 64 / NTE, 256, E_SMEMB>>>(state, encW, encb, B);

    dim3 grid(B / 128 / NT, NPAIR);
    critic_kernel<<<grid, 256, K_SMEMB>>>(acs, eW1, eb1, eW2, eb2,
                                          iW1, ib1, iW2, ib2, out, B);
}

// round 7
// speedup vs baseline: 1.5014x; 1.3348x over previous
#include <cuda_runtime.h>
#include <cuda_fp16.h>
#include <cstdint>

// ---------------------------------------------------------------------------
// CentralCritic, critic GEMM on fp16 mma.sync.m16n8k16 (f32 accumulate).
//   cvt:    acs fp32 -> g_acsh fp16 (GEMM operand only; argmax stays fp32)
//   enc:    relu(state @ encW + b) -> g_ench (fp16), tf32 mma internally
//   critic: h = relu([acs_loo|enc] @ W1 + b1); out = h . W2[:,argmax] + b2
// fp16 has the same 11-bit significand as tf32 -> rel_err preserved,
// but m16n8k16 doubles K per HMMA -> tensor-issue time halves.
// ---------------------------------------------------------------------------

#define A_   4
#define H_   3
#define HI_  2
#define C_   16
#define S_   256
#define D_   128
#define IN_  176
#define NPAIR 20
#define NT    8      // 128-row tiles per critic CTA
#define NTE   4      // 64-row tiles per enc CTA

// enc kernel strides (floats)
#define WS_ST  136
#define XE_ST  260

// critic smem layout (float/uint32 offsets)
#define WP_OFF   0                       // 88*136 u32 = 11968
#define X0_OFF   11968                   // 128*52 u32 = 6656
#define X1_OFF   18624                   // 128*44 u32 = 5632
#define W2_OFF   24256                   // 128*17 = 2176
#define B1_OFF   26432                   // 128
#define B2_OFF   26560                   // 16
#define PART_OFF 26576                   // 256
#define CIDX_OFF 26832                   // 128
#define K_SMEMB  (26960 * 4)             // 107840 B

// enc smem offsets (floats)
#define WSE_OFF  0
#define XSE_OFF  34816
#define BE_OFF   51456
#define E_SMEMB  (51584 * 4)

__device__ __half g_ench[32768 * D_];            // enc activations, fp16
__device__ __half g_acsh[A_ * H_ * 32768 * C_];  // acs, fp16 (GEMM operand)

__constant__ int c_loo[4][3] = {{1,2,3},{0,2,3},{0,1,3},{0,1,2}};

// ---- helpers ---------------------------------------------------------------
__device__ __forceinline__ uint32_t smem_u32(const void* p) {
    uint32_t r;
    asm("{ .reg .u64 t; cvta.to.shared.u64 t, %1; cvt.u32.u64 %0, t; }"
        : "=r"(r) : "l"(p));
    return r;
}
__device__ __forceinline__ uint32_t tf32r(float x) {
    uint32_t y; asm("cvt.rna.tf32.f32 %0, %1;" : "=r"(y) : "f"(x)); return y;
}
__device__ __forceinline__ void cpasync16(uint32_t dst, const void* src) {
    asm volatile("cp.async.cg.shared.global [%0], [%1], 16;"
                 :: "r"(dst), "l"(src));
}
#define CPCOMMIT()  asm volatile("cp.async.commit_group;" ::: "memory")
#define CPWAITG(n)  asm volatile("cp.async.wait_group %0;" :: "n"(n) : "memory")

// tf32 k8 (enc kernel)
__device__ __forceinline__ void mma8(float* d, const uint32_t* a,
                                     const uint32_t* b) {
    asm volatile(
        "mma.sync.aligned.m16n8k8.row.col.f32.tf32.tf32.f32 "
        "{%0,%1,%2,%3}, {%4,%5,%6,%7}, {%8,%9}, {%0,%1,%2,%3};"
        : "+f"(d[0]), "+f"(d[1]), "+f"(d[2]), "+f"(d[3])
        : "r"(a[0]), "r"(a[1]), "r"(a[2]), "r"(a[3]), "r"(b[0]), "r"(b[1]));
}
// fp16 k16 (critic kernel)
__device__ __forceinline__ void mma16(float* d, const uint32_t* a,
                                      const uint32_t* b) {
    asm volatile(
        "mma.sync.aligned.m16n8k16.row.col.f32.f16.f16.f32 "
        "{%0,%1,%2,%3}, {%4,%5,%6,%7}, {%8,%9}, {%0,%1,%2,%3};"
        : "+f"(d[0]), "+f"(d[1]), "+f"(d[2]), "+f"(d[3])
        : "r"(a[0]), "r"(a[1]), "r"(a[2]), "r"(a[3]), "r"(b[0]), "r"(b[1]));
}

// ---------------------------------------------------------------------------
// acs fp32 -> fp16 (layout preserved)
// ---------------------------------------------------------------------------
__global__ __launch_bounds__(256) void cvt_acs_kernel(
    const float* __restrict__ acs, int n4)       // n4 = total/4
{
    int idx = blockIdx.x * 256 + threadIdx.x;
    if (idx >= n4) return;
    float4 v = *(const float4*)(acs + (size_t)idx * 4);
    __half2 h0 = __floats2half2_rn(v.x, v.y);
    __half2 h1 = __floats2half2_rn(v.z, v.w);
    uint2 o; o.x = *(uint32_t*)&h0; o.y = *(uint32_t*)&h1;
    *(uint2*)(g_acsh + (size_t)idx * 4) = o;
}

// ---------------------------------------------------------------------------
// encoder: relu(state @ encW + b) -> g_ench (fp16). tf32 MMA internals.
// ---------------------------------------------------------------------------
__global__ __launch_bounds__(256, 1) void enc_kernel(
    const float* __restrict__ state, const float* __restrict__ encW,
    const float* __restrict__ encb, int B)
{
    extern __shared__ float smf[];
    const int tid = threadIdx.x, wid = tid >> 5, lane = tid & 31;
    const int g = lane >> 2, t = lane & 3;
    const int wm = wid >> 2, wn = wid & 3;
    const int wr = wm * 32, wc = wn * 32;

    for (int it = 0; it < 32; it++) {
        int fi = it * 256 + tid;
        int k = fi >> 5, n4 = fi & 31;
        float4 v = *(const float4*)(encW + (size_t)k * D_ + n4 * 4);
        uint4 w; w.x = tf32r(v.x); w.y = tf32r(v.y);
        w.z = tf32r(v.z); w.w = tf32r(v.w);
        *(uint4*)(smf + WSE_OFF + k * WS_ST + n4 * 4) = w;
    }
    if (tid < D_) smf[BE_OFF + tid] = encb[tid];

    const uint32_t xbase = smem_u32(smf + XSE_OFF);
    const int tile0 = blockIdx.x * NTE;

    {
        int row0 = tile0 * 64;
        for (int it = 0; it < 16; it++) {
            int idx = it * 256 + tid;
            int c = idx & 63, row = idx >> 6;
            cpasync16(xbase + (uint32_t)(row * XE_ST + c * 4) * 4,
                      state + (size_t)(row0 + row) * S_ + c * 4);
        }
        CPCOMMIT();
    }
    CPWAITG(0);
    __syncthreads();

    for (int tt = 0; tt < NTE; tt++) {
        const int row0 = (tile0 + tt) * 64;
        float acc[2][4][4];
#pragma unroll
        for (int mi = 0; mi < 2; mi++)
#pragma unroll
            for (int ni = 0; ni < 4; ni++)
#pragma unroll
                for (int e = 0; e < 4; e++) acc[mi][ni][e] = 0.f;

        const uint32_t* Xu = (const uint32_t*)(smf + XSE_OFF);
        const uint32_t* Wu = (const uint32_t*)(smf + WSE_OFF);
#pragma unroll
        for (int ks = 0; ks < 32; ks++) {
            const int k0 = ks * 8;
            uint32_t a[2][4], b[4][2];
#pragma unroll
            for (int mi = 0; mi < 2; mi++) {
                int r = wr + mi * 16 + g;
                a[mi][0] = Xu[r * XE_ST + k0 + t];
                a[mi][1] = Xu[(r + 8) * XE_ST + k0 + t];
                a[mi][2] = Xu[r * XE_ST + k0 + t + 4];
                a[mi][3] = Xu[(r + 8) * XE_ST + k0 + t + 4];
            }
#pragma unroll
            for (int ni = 0; ni < 4; ni++) {
                int n = wc + ni * 8 + g;
                b[ni][0] = Wu[(k0 + t) * WS_ST + n];
                b[ni][1] = Wu[(k0 + t + 4) * WS_ST + n];
            }
#pragma unroll
            for (int mi = 0; mi < 2; mi++)
#pragma unroll
                for (int ni = 0; ni < 4; ni++)
                    mma8(acc[mi][ni], a[mi], b[ni]);
        }
        __syncthreads();

        if (tt + 1 < NTE) {
            int nrow0 = (tile0 + tt + 1) * 64;
            for (int it = 0; it < 16; it++) {
                int idx = it * 256 + tid;
                int c = idx & 63, row = idx >> 6;
                cpasync16(xbase + (uint32_t)(row * XE_ST + c * 4) * 4,
                          state + (size_t)(nrow0 + row) * S_ + c * 4);
            }
            CPCOMMIT();
        }

        // epilogue: bias + relu -> fp16 pairs
#pragma unroll
        for (int mi = 0; mi < 2; mi++) {
            int r0 = row0 + wr + mi * 16 + g;
#pragma unroll
            for (int ni = 0; ni < 4; ni++) {
                int col = wc + ni * 8 + 2 * t;
                float b0 = smf[BE_OFF + col], b1v = smf[BE_OFF + col + 1];
                __half2 h0 = __floats2half2_rn(
                    fmaxf(acc[mi][ni][0] + b0, 0.f),
                    fmaxf(acc[mi][ni][1] + b1v, 0.f));
                __half2 h1 = __floats2half2_rn(
                    fmaxf(acc[mi][ni][2] + b0, 0.f),
                    fmaxf(acc[mi][ni][3] + b1v, 0.f));
                *(__half2*)(g_ench + (size_t)r0 * D_ + col) = h0;
                *(__half2*)(g_ench + (size_t)(r0 + 8) * D_ + col) = h1;
            }
        }

        if (tt + 1 < NTE) CPWAITG(0);
        __syncthreads();
    }
}

// ---------------------------------------------------------------------------
// critic: 256 thr, 8 warps (4 wm x 2 wn), warp tile 32x64, fp16 m16n8k16.
// K=176 -> 11 k16-steps: half0 = 6 (k 0..95), half1 = 5 (k 96..175).
// ---------------------------------------------------------------------------
__global__ __launch_bounds__(256, 1) void critic_kernel(
    const float* __restrict__ acs,
    const float* __restrict__ eW1, const float* __restrict__ eb1,
    const float* __restrict__ eW2, const float* __restrict__ eb2,
    const float* __restrict__ iW1, const float* __restrict__ ib1,
    const float* __restrict__ iW2, const float* __restrict__ ib2,
    float* __restrict__ out, int B)
{
    extern __shared__ float smf[];
    const int tid = threadIdx.x, wid = tid >> 5, lane = tid & 31;
    const int g = lane >> 2, t = lane & 3;
    const int wm = wid >> 1, wn = wid & 1;
    const int wr = wm * 32, wc = wn * 64;
    const int p = blockIdx.y;

    int i, head;
    const float *W1, *b1, *W2, *b2;
    float* outp;
    if (p < A_ * H_) {
        i = p / H_; int j = p % H_; head = j;
        W1 = eW1 + (size_t)(j * A_ + i) * IN_ * D_;
        b1 = eb1 + (size_t)(j * A_ + i) * D_;
        W2 = eW2 + (size_t)(j * A_ + i) * D_ * C_;
        b2 = eb2 + (size_t)(j * A_ + i) * C_;
        outp = out + (size_t)p * B;
    } else {
        int q = p - A_ * H_;
        i = q / HI_; int j = q % HI_; head = j + 1;
        W1 = iW1 + (size_t)(j * A_ + i) * IN_ * D_;
        b1 = ib1 + (size_t)(j * A_ + i) * D_;
        W2 = iW2 + (size_t)(j * A_ + i) * D_ * C_;
        b2 = ib2 + (size_t)(j * A_ + i) * C_;
        outp = out + (size_t)(A_ * H_) * B + (size_t)q * B;
    }
    const __half* acsA[3];
    acsA[0] = g_acsh + (size_t)(c_loo[i][0] * H_ + head) * B * C_;
    acsA[1] = g_acsh + (size_t)(c_loo[i][1] * H_ + head) * B * C_;
    acsA[2] = g_acsh + (size_t)(c_loo[i][2] * H_ + head) * B * C_;
    const float* acsSelf = acs + (size_t)(i * H_ + head) * B * C_;

    // ---- stage W1 as fp16 k-pair-packed: Wp[k>>1][n] u32, stride 136 ----
    __half* Wph = (__half*)(smf + WP_OFF);
    for (int it = 0; it < 22; it++) {
        int fi = it * 256 + tid;            // 5632 float4
        int k = fi >> 5, n0 = (fi & 31) * 4;
        float4 v = *(const float4*)(W1 + (size_t)k * D_ + n0);
        int base = ((k >> 1) * 136 + n0) * 2 + (k & 1);
        Wph[base + 0] = __float2half_rn(v.x);
        Wph[base + 2] = __float2half_rn(v.y);
        Wph[base + 4] = __float2half_rn(v.z);
        Wph[base + 6] = __float2half_rn(v.w);
    }
    for (int it = 0; it < 8; it++) {
        int idx = it * 256 + tid;           // 2048 floats
        int d = idx >> 4, c = idx & 15;
        smf[W2_OFF + d * 17 + c] = W2[idx];
    }
    if (tid < D_) smf[B1_OFF + tid] = b1[tid];
    if (tid < C_) smf[B2_OFF + tid] = b2[tid];

    const uint32_t x0b = smem_u32(smf + X0_OFF);
    const uint32_t x1b = smem_u32(smf + X1_OFF);
    const int tile0 = blockIdx.x * NT;
    int* cidx = (int*)(smf + CIDX_OFF);

    // buf0: 12 chunks/row (acs 6 + enc[0..47] 6), 1536 chunks, 6 iters
    auto stage_buf0 = [&](int row0) {
#pragma unroll
        for (int it = 0; it < 6; it++) {
            int idx = it * 256 + tid;
            int row = idx / 12, c = idx - (idx / 12) * 12;
            const void* src;
            if (c < 6)
                src = acsA[c >> 1] + (size_t)(row0 + row) * C_ + (c & 1) * 8;
            else
                src = g_ench + (size_t)(row0 + row) * D_ + (c - 6) * 8;
            cpasync16(x0b + (uint32_t)(row * 52 + c * 4) * 4, src);
        }
        CPCOMMIT();
    };
    // buf1: enc[48..127], 10 chunks/row, 1280 chunks, 5 iters
    auto stage_buf1 = [&](int row0) {
#pragma unroll
        for (int it = 0; it < 5; it++) {
            int idx = it * 256 + tid;
            int row = idx / 10, u = idx - (idx / 10) * 10;
            const void* src = g_ench + (size_t)(row0 + row) * D_ + 48 + u * 8;
            cpasync16(x1b + (uint32_t)(row * 44 + u * 4) * 4, src);
        }
        CPCOMMIT();
    };

    stage_buf0(tile0 * 128);
    stage_buf1(tile0 * 128);

    const uint32_t* X0 = (const uint32_t*)(smf + X0_OFF);
    const uint32_t* X1 = (const uint32_t*)(smf + X1_OFF);
    const uint32_t* Wp = (const uint32_t*)(smf + WP_OFF);

    for (int tt = 0; tt < NT; tt++) {
        const int row0 = (tile0 + tt) * 128;
        float acc[2][8][4];
#pragma unroll
        for (int mi = 0; mi < 2; mi++)
#pragma unroll
            for (int ni = 0; ni < 8; ni++)
#pragma unroll
                for (int e = 0; e < 4; e++) acc[mi][ni][e] = 0.f;

        // ---- half 0: ks 0..5 ----
        CPWAITG(1);
        __syncthreads();
#pragma unroll
        for (int ks = 0; ks < 6; ks++) {
            const int k0 = ks * 8;
            uint32_t a[2][4], b[8][2];
#pragma unroll
            for (int mi = 0; mi < 2; mi++) {
                int r = wr + mi * 16 + g;
                a[mi][0] = X0[r * 52 + k0 + t];
                a[mi][1] = X0[(r + 8) * 52 + k0 + t];
                a[mi][2] = X0[r * 52 + k0 + t + 4];
                a[mi][3] = X0[(r + 8) * 52 + k0 + t + 4];
            }
#pragma unroll
            for (int ni = 0; ni < 8; ni++) {
                int n = wc + ni * 8 + g;
                b[ni][0] = Wp[(k0 + t) * 136 + n];
                b[ni][1] = Wp[(k0 + t + 4) * 136 + n];
            }
#pragma unroll
            for (int mi = 0; mi < 2; mi++)
#pragma unroll
                for (int ni = 0; ni < 8; ni++)
                    mma16(acc[mi][ni], a[mi], b[ni]);
        }
        __syncthreads();
        if (tt + 1 < NT) stage_buf0((tile0 + tt + 1) * 128);

        // argmax from fp32 acs (overlaps cp.async flight)
        if (tid < 128) {
            const float* ar = acsSelf + (size_t)(row0 + tid) * C_;
            float4 v0 = *(const float4*)ar;
            float4 v1 = *(const float4*)(ar + 4);
            float4 v2 = *(const float4*)(ar + 8);
            float4 v3 = *(const float4*)(ar + 12);
            float vv[16] = {v0.x,v0.y,v0.z,v0.w, v1.x,v1.y,v1.z,v1.w,
                            v2.x,v2.y,v2.z,v2.w, v3.x,v3.y,v3.z,v3.w};
            float best = vv[0]; int c = 0;
#pragma unroll
            for (int cc = 1; cc < C_; cc++)
                if (vv[cc] > best) { best = vv[cc]; c = cc; }
            cidx[tid] = c;
        }

        // ---- half 1: ks 6..10 ----
        if (tt + 1 < NT) { CPWAITG(1); } else { CPWAITG(0); }
        __syncthreads();
#pragma unroll
        for (int ks = 6; ks < 11; ks++) {
            const int k0l = (ks - 6) * 8;      // X1 local
            const int kw = ks * 8;             // Wp global
            uint32_t a[2][4], b[8][2];
#pragma unroll
            for (int mi = 0; mi < 2; mi++) {
                int r = wr + mi * 16 + g;
                a[mi][0] = X1[r * 44 + k0l + t];
                a[mi][1] = X1[(r + 8) * 44 + k0l + t];
                a[mi][2] = X1[r * 44 + k0l + t + 4];
                a[mi][3] = X1[(r + 8) * 44 + k0l + t + 4];
            }
#pragma unroll
            for (int ni = 0; ni < 8; ni++) {
                int n = wc + ni * 8 + g;
                b[ni][0] = Wp[(kw + t) * 136 + n];
                b[ni][1] = Wp[(kw + t + 4) * 136 + n];
            }
#pragma unroll
            for (int mi = 0; mi < 2; mi++)
#pragma unroll
                for (int ni = 0; ni < 8; ni++)
                    mma16(acc[mi][ni], a[mi], b[ni]);
        }
        __syncthreads();       // buf1 consumed + cidx visible
        if (tt + 1 < NT) stage_buf1((tile0 + tt + 1) * 128);

        // ---- epilogue: relu(acc+b1) . W2[:,c], 2-way N reduction ----
#pragma unroll
        for (int mi = 0; mi < 2; mi++) {
            int r0 = wr + mi * 16 + g;
            int cR0 = cidx[r0], cR1 = cidx[r0 + 8];
            float s0 = 0.f, s1 = 0.f;
#pragma unroll
            for (int ni = 0; ni < 8; ni++) {
                int col0 = wc + ni * 8 + 2 * t;
                float bb0 = smf[B1_OFF + col0], bb1 = smf[B1_OFF + col0 + 1];
                float w00 = smf[W2_OFF + col0 * 17 + cR0];
                float w01 = smf[W2_OFF + (col0 + 1) * 17 + cR0];
                float w10 = smf[W2_OFF + col0 * 17 + cR1];
                float w11 = smf[W2_OFF + (col0 + 1) * 17 + cR1];
                s0 += fmaxf(acc[mi][ni][0] + bb0, 0.f) * w00
                    + fmaxf(acc[mi][ni][1] + bb1, 0.f) * w01;
                s1 += fmaxf(acc[mi][ni][2] + bb0, 0.f) * w10
                    + fmaxf(acc[mi][ni][3] + bb1, 0.f) * w11;
            }
            s0 += __shfl_xor_sync(0xffffffffu, s0, 1);
            s0 += __shfl_xor_sync(0xffffffffu, s0, 2);
            s1 += __shfl_xor_sync(0xffffffffu, s1, 1);
            s1 += __shfl_xor_sync(0xffffffffu, s1, 2);
            if (t == 0) {
                smf[PART_OFF + wn * 128 + r0] = s0;
                smf[PART_OFF + wn * 128 + r0 + 8] = s1;
            }
        }
        __syncthreads();
        if (tid < 128) {
            float q = smf[PART_OFF + tid] + smf[PART_OFF + 128 + tid]
                    + smf[B2_OFF + cidx[tid]];
            outp[row0 + tid] = q;
        }
        __syncthreads();
    }
}

// ---------------------------------------------------------------------------
extern "C" void kernel_launch(void* const* d_in, const int* in_sizes, int n_in,
                              void* d_out, int out_size)
{
    const float* state = (const float*)d_in[0];
    const float* acs   = (const float*)d_in[1];
    const float* encW  = (const float*)d_in[2];
    const float* encb  = (const float*)d_in[3];
    const float* eW1   = (const float*)d_in[4];
    const float* eb1   = (const float*)d_in[5];
    const float* eW2   = (const float*)d_in[6];
    const float* eb2   = (const float*)d_in[7];
    const float* iW1   = (const float*)d_in[8];
    const float* ib1   = (const float*)d_in[9];
    const float* iW2   = (const float*)d_in[10];
    const float* ib2   = (const float*)d_in[11];
    float* out = (float*)d_out;

    const int B = in_sizes[0] / S_;          // 32768
    const int acs_n4 = A_ * H_ * B * C_ / 4;

    cudaFuncSetAttribute(enc_kernel,
        cudaFuncAttributeMaxDynamicSharedMemorySize, E_SMEMB);
    cudaFuncSetAttribute(critic_kernel,
        cudaFuncAttributeMaxDynamicSharedMemorySize, K_SMEMB);

    cvt_acs_kernel<<<(acs_n4 + 255) / 256, 256>>>(acs, acs_n4);
    enc_kernel<<<B / 64 / NTE, 256, E_SMEMB>>>(state, encW, encb, B);

    dim3 grid(B / 128 / NT, NPAIR);
    critic_kernel<<<grid, 256, K_SMEMB>>>(acs, eW1, eb1, eW2, eb2,
                                          iW1, ib1, iW2, ib2, out, B);
}

// round 8
// speedup vs baseline: 1.6097x; 1.0721x over previous
#include <cuda_runtime.h>
#include <cuda_fp16.h>
#include <cstdint>

// ---------------------------------------------------------------------------
// CentralCritic, critic GEMM on fp16 mma.sync.m16n8k16 (f32 accumulate).
//   enc:    acs fp32->fp16 (folded prologue), then
//           relu(state @ encW + b) -> g_ench (fp16), tf32 mma
//   critic: h = relu([acs_loo|enc] @ W1 + b1); out = h . W2[:,argmax] + b2
// R8: critic runs 2 CTAs/SM (128-reg cap, fp16 frags fit) so one CTA's
//     syncs/epilogue overlap the other's MMA; cvt kernel folded into enc.
// ---------------------------------------------------------------------------

#define A_   4
#define H_   3
#define HI_  2
#define C_   16
#define S_   256
#define D_   128
#define IN_  176
#define NPAIR 20
#define NT    8      // 128-row tiles per critic CTA
#define NTE   4      // 64-row tiles per enc CTA

// enc kernel strides (floats)
#define WS_ST  136
#define XE_ST  260

// critic smem layout (float/uint32 offsets)
#define WP_OFF   0                       // 88*136 u32 = 11968
#define X0_OFF   11968                   // 128*52 u32 = 6656
#define X1_OFF   18624                   // 128*44 u32 = 5632
#define W2_OFF   24256                   // 128*17 = 2176
#define B1_OFF   26432                   // 128
#define B2_OFF   26560                   // 16
#define PART_OFF 26576                   // 256
#define CIDX_OFF 26832                   // 128
#define K_SMEMB  (26960 * 4)             // 107840 B  (x2 = 215680 <= 228KB)

// enc smem offsets (floats)
#define WSE_OFF  0
#define XSE_OFF  34816
#define BE_OFF   51456
#define E_SMEMB  (51584 * 4)

__device__ __half g_ench[32768 * D_];            // enc activations, fp16
__device__ __half g_acsh[A_ * H_ * 32768 * C_];  // acs, fp16 (GEMM operand)

__constant__ int c_loo[4][3] = {{1,2,3},{0,2,3},{0,1,3},{0,1,2}};

// ---- helpers ---------------------------------------------------------------
__device__ __forceinline__ uint32_t smem_u32(const void* p) {
    uint32_t r;
    asm("{ .reg .u64 t; cvta.to.shared.u64 t, %1; cvt.u32.u64 %0, t; }"
        : "=r"(r) : "l"(p));
    return r;
}
__device__ __forceinline__ uint32_t tf32r(float x) {
    uint32_t y; asm("cvt.rna.tf32.f32 %0, %1;" : "=r"(y) : "f"(x)); return y;
}
__device__ __forceinline__ void cpasync16(uint32_t dst, const void* src) {
    asm volatile("cp.async.cg.shared.global [%0], [%1], 16;"
                 :: "r"(dst), "l"(src));
}
#define CPCOMMIT()  asm volatile("cp.async.commit_group;" ::: "memory")
#define CPWAITG(n)  asm volatile("cp.async.wait_group %0;" :: "n"(n) : "memory")

// tf32 k8 (enc kernel)
__device__ __forceinline__ void mma8(float* d, const uint32_t* a,
                                     const uint32_t* b) {
    asm volatile(
        "mma.sync.aligned.m16n8k8.row.col.f32.tf32.tf32.f32 "
        "{%0,%1,%2,%3}, {%4,%5,%6,%7}, {%8,%9}, {%0,%1,%2,%3};"
        : "+f"(d[0]), "+f"(d[1]), "+f"(d[2]), "+f"(d[3])
        : "r"(a[0]), "r"(a[1]), "r"(a[2]), "r"(a[3]), "r"(b[0]), "r"(b[1]));
}
// fp16 k16 (critic kernel)
__device__ __forceinline__ void mma16(float* d, const uint32_t* a,
                                      const uint32_t* b) {
    asm volatile(
        "mma.sync.aligned.m16n8k16.row.col.f32.f16.f16.f32 "
        "{%0,%1,%2,%3}, {%4,%5,%6,%7}, {%8,%9}, {%0,%1,%2,%3};"
        : "+f"(d[0]), "+f"(d[1]), "+f"(d[2]), "+f"(d[3])
        : "r"(a[0]), "r"(a[1]), "r"(a[2]), "r"(a[3]), "r"(b[0]), "r"(b[1]));
}

// ---------------------------------------------------------------------------
// encoder: acs->fp16 prologue, then relu(state @ encW + b) -> g_ench (fp16).
// ---------------------------------------------------------------------------
__global__ __launch_bounds__(256, 1) void enc_kernel(
    const float* __restrict__ state, const float* __restrict__ encW,
    const float* __restrict__ encb, const float* __restrict__ acs, int B)
{
    extern __shared__ float smf[];
    const int tid = threadIdx.x, wid = tid >> 5, lane = tid & 31;
    const int g = lane >> 2, t = lane & 3;
    const int wm = wid >> 2, wn = wid & 3;
    const int wr = wm * 32, wc = wn * 32;
    const int gthr = blockIdx.x * 256 + tid;
    const int nthr = gridDim.x * 256;

    // ---- folded acs fp32 -> fp16 conversion (layout preserved) ----
    {
        const int n4 = A_ * H_ * B * C_ / 4;
        for (int idx = gthr; idx < n4; idx += nthr) {
            float4 v = *(const float4*)(acs + (size_t)idx * 4);
            __half2 h0 = __floats2half2_rn(v.x, v.y);
            __half2 h1 = __floats2half2_rn(v.z, v.w);
            uint2 o; o.x = *(uint32_t*)&h0; o.y = *(uint32_t*)&h1;
            *(uint2*)(g_acsh + (size_t)idx * 4) = o;
        }
    }

    for (int it = 0; it < 32; it++) {
        int fi = it * 256 + tid;
        int k = fi >> 5, n4 = fi & 31;
        float4 v = *(const float4*)(encW + (size_t)k * D_ + n4 * 4);
        uint4 w; w.x = tf32r(v.x); w.y = tf32r(v.y);
        w.z = tf32r(v.z); w.w = tf32r(v.w);
        *(uint4*)(smf + WSE_OFF + k * WS_ST + n4 * 4) = w;
    }
    if (tid < D_) smf[BE_OFF + tid] = encb[tid];

    const uint32_t xbase = smem_u32(smf + XSE_OFF);
    const int tile0 = blockIdx.x * NTE;

    {
        int row0 = tile0 * 64;
        for (int it = 0; it < 16; it++) {
            int idx = it * 256 + tid;
            int c = idx & 63, row = idx >> 6;
            cpasync16(xbase + (uint32_t)(row * XE_ST + c * 4) * 4,
                      state + (size_t)(row0 + row) * S_ + c * 4);
        }
        CPCOMMIT();
    }
    CPWAITG(0);
    __syncthreads();

    for (int tt = 0; tt < NTE; tt++) {
        const int row0 = (tile0 + tt) * 64;
        float acc[2][4][4];
#pragma unroll
        for (int mi = 0; mi < 2; mi++)
#pragma unroll
            for (int ni = 0; ni < 4; ni++)
#pragma unroll
                for (int e = 0; e < 4; e++) acc[mi][ni][e] = 0.f;

        const uint32_t* Xu = (const uint32_t*)(smf + XSE_OFF);
        const uint32_t* Wu = (const uint32_t*)(smf + WSE_OFF);
#pragma unroll
        for (int ks = 0; ks < 32; ks++) {
            const int k0 = ks * 8;
            uint32_t a[2][4], b[4][2];
#pragma unroll
            for (int mi = 0; mi < 2; mi++) {
                int r = wr + mi * 16 + g;
                a[mi][0] = Xu[r * XE_ST + k0 + t];
                a[mi][1] = Xu[(r + 8) * XE_ST + k0 + t];
                a[mi][2] = Xu[r * XE_ST + k0 + t + 4];
                a[mi][3] = Xu[(r + 8) * XE_ST + k0 + t + 4];
            }
#pragma unroll
            for (int ni = 0; ni < 4; ni++) {
                int n = wc + ni * 8 + g;
                b[ni][0] = Wu[(k0 + t) * WS_ST + n];
                b[ni][1] = Wu[(k0 + t + 4) * WS_ST + n];
            }
#pragma unroll
            for (int mi = 0; mi < 2; mi++)
#pragma unroll
                for (int ni = 0; ni < 4; ni++)
                    mma8(acc[mi][ni], a[mi], b[ni]);
        }
        __syncthreads();

        if (tt + 1 < NTE) {
            int nrow0 = (tile0 + tt + 1) * 64;
            for (int it = 0; it < 16; it++) {
                int idx = it * 256 + tid;
                int c = idx & 63, row = idx >> 6;
                cpasync16(xbase + (uint32_t)(row * XE_ST + c * 4) * 4,
                          state + (size_t)(nrow0 + row) * S_ + c * 4);
            }
            CPCOMMIT();
        }

        // epilogue: bias + relu -> fp16 pairs
#pragma unroll
        for (int mi = 0; mi < 2; mi++) {
            int r0 = row0 + wr + mi * 16 + g;
#pragma unroll
            for (int ni = 0; ni < 4; ni++) {
                int col = wc + ni * 8 + 2 * t;
                float b0 = smf[BE_OFF + col], b1v = smf[BE_OFF + col + 1];
                __half2 h0 = __floats2half2_rn(
                    fmaxf(acc[mi][ni][0] + b0, 0.f),
                    fmaxf(acc[mi][ni][1] + b1v, 0.f));
                __half2 h1 = __floats2half2_rn(
                    fmaxf(acc[mi][ni][2] + b0, 0.f),
                    fmaxf(acc[mi][ni][3] + b1v, 0.f));
                *(__half2*)(g_ench + (size_t)r0 * D_ + col) = h0;
                *(__half2*)(g_ench + (size_t)(r0 + 8) * D_ + col) = h1;
            }
        }

        if (tt + 1 < NTE) CPWAITG(0);
        __syncthreads();
    }
}

// ---------------------------------------------------------------------------
// critic: 256 thr, 8 warps (4 wm x 2 wn), warp tile 32x64, fp16 m16n8k16,
// 2 CTAs/SM (128-reg cap).
// ---------------------------------------------------------------------------
__global__ __launch_bounds__(256, 2) void critic_kernel(
    const float* __restrict__ acs,
    const float* __restrict__ eW1, const float* __restrict__ eb1,
    const float* __restrict__ eW2, const float* __restrict__ eb2,
    const float* __restrict__ iW1, const float* __restrict__ ib1,
    const float* __restrict__ iW2, const float* __restrict__ ib2,
    float* __restrict__ out, int B)
{
    extern __shared__ float smf[];
    const int tid = threadIdx.x, wid = tid >> 5, lane = tid & 31;
    const int g = lane >> 2, t = lane & 3;
    const int wm = wid >> 1, wn = wid & 1;
    const int wr = wm * 32, wc = wn * 64;
    const int p = blockIdx.y;

    int i, head;
    const float *W1, *b1, *W2, *b2;
    float* outp;
    if (p < A_ * H_) {
        i = p / H_; int j = p % H_; head = j;
        W1 = eW1 + (size_t)(j * A_ + i) * IN_ * D_;
        b1 = eb1 + (size_t)(j * A_ + i) * D_;
        W2 = eW2 + (size_t)(j * A_ + i) * D_ * C_;
        b2 = eb2 + (size_t)(j * A_ + i) * C_;
        outp = out + (size_t)p * B;
    } else {
        int q = p - A_ * H_;
        i = q / HI_; int j = q % HI_; head = j + 1;
        W1 = iW1 + (size_t)(j * A_ + i) * IN_ * D_;
        b1 = ib1 + (size_t)(j * A_ + i) * D_;
        W2 = iW2 + (size_t)(j * A_ + i) * D_ * C_;
        b2 = ib2 + (size_t)(j * A_ + i) * C_;
        outp = out + (size_t)(A_ * H_) * B + (size_t)q * B;
    }
    const __half* acsA[3];
    acsA[0] = g_acsh + (size_t)(c_loo[i][0] * H_ + head) * B * C_;
    acsA[1] = g_acsh + (size_t)(c_loo[i][1] * H_ + head) * B * C_;
    acsA[2] = g_acsh + (size_t)(c_loo[i][2] * H_ + head) * B * C_;
    const float* acsSelf = acs + (size_t)(i * H_ + head) * B * C_;

    // ---- stage W1 as fp16 k-pair-packed: Wp[k>>1][n] u32, stride 136 ----
    __half* Wph = (__half*)(smf + WP_OFF);
    for (int it = 0; it < 22; it++) {
        int fi = it * 256 + tid;            // 5632 float4
        int k = fi >> 5, n0 = (fi & 31) * 4;
        float4 v = *(const float4*)(W1 + (size_t)k * D_ + n0);
        int base = ((k >> 1) * 136 + n0) * 2 + (k & 1);
        Wph[base + 0] = __float2half_rn(v.x);
        Wph[base + 2] = __float2half_rn(v.y);
        Wph[base + 4] = __float2half_rn(v.z);
        Wph[base + 6] = __float2half_rn(v.w);
    }
    for (int it = 0; it < 8; it++) {
        int idx = it * 256 + tid;           // 2048 floats
        int d = idx >> 4, c = idx & 15;
        smf[W2_OFF + d * 17 + c] = W2[idx];
    }
    if (tid < D_) smf[B1_OFF + tid] = b1[tid];
    if (tid < C_) smf[B2_OFF + tid] = b2[tid];

    const uint32_t x0b = smem_u32(smf + X0_OFF);
    const uint32_t x1b = smem_u32(smf + X1_OFF);
    const int tile0 = blockIdx.x * NT;
    int* cidx = (int*)(smf + CIDX_OFF);

    // buf0: 12 chunks/row (acs 6 + enc[0..47] 6), 1536 chunks, 6 iters
    auto stage_buf0 = [&](int row0) {
#pragma unroll
        for (int it = 0; it < 6; it++) {
            int idx = it * 256 + tid;
            int row = idx / 12, c = idx - (idx / 12) * 12;
            const void* src;
            if (c < 6)
                src = acsA[c >> 1] + (size_t)(row0 + row) * C_ + (c & 1) * 8;
            else
                src = g_ench + (size_t)(row0 + row) * D_ + (c - 6) * 8;
            cpasync16(x0b + (uint32_t)(row * 52 + c * 4) * 4, src);
        }
        CPCOMMIT();
    };
    // buf1: enc[48..127], 10 chunks/row, 1280 chunks, 5 iters
    auto stage_buf1 = [&](int row0) {
#pragma unroll
        for (int it = 0; it < 5; it++) {
            int idx = it * 256 + tid;
            int row = idx / 10, u = idx - (idx / 10) * 10;
            const void* src = g_ench + (size_t)(row0 + row) * D_ + 48 + u * 8;
            cpasync16(x1b + (uint32_t)(row * 44 + u * 4) * 4, src);
        }
        CPCOMMIT();
    };

    stage_buf0(tile0 * 128);
    stage_buf1(tile0 * 128);

    const uint32_t* X0 = (const uint32_t*)(smf + X0_OFF);
    const uint32_t* X1 = (const uint32_t*)(smf + X1_OFF);
    const uint32_t* Wp = (const uint32_t*)(smf + WP_OFF);

    for (int tt = 0; tt < NT; tt++) {
        const int row0 = (tile0 + tt) * 128;
        float acc[2][8][4];
#pragma unroll
        for (int mi = 0; mi < 2; mi++)
#pragma unroll
            for (int ni = 0; ni < 8; ni++)
#pragma unroll
                for (int e = 0; e < 4; e++) acc[mi][ni][e] = 0.f;

        // ---- half 0: ks 0..5 ----
        CPWAITG(1);
        __syncthreads();
#pragma unroll
        for (int ks = 0; ks < 6; ks++) {
            const int k0 = ks * 8;
            uint32_t a[2][4], b[8][2];
#pragma unroll
            for (int mi = 0; mi < 2; mi++) {
                int r = wr + mi * 16 + g;
                a[mi][0] = X0[r * 52 + k0 + t];
                a[mi][1] = X0[(r + 8) * 52 + k0 + t];
                a[mi][2] = X0[r * 52 + k0 + t + 4];
                a[mi][3] = X0[(r + 8) * 52 + k0 + t + 4];
            }
#pragma unroll
            for (int ni = 0; ni < 8; ni++) {
                int n = wc + ni * 8 + g;
                b[ni][0] = Wp[(k0 + t) * 136 + n];
                b[ni][1] = Wp[(k0 + t + 4) * 136 + n];
            }
#pragma unroll
            for (int mi = 0; mi < 2; mi++)
#pragma unroll
                for (int ni = 0; ni < 8; ni++)
                    mma16(acc[mi][ni], a[mi], b[ni]);
        }
        __syncthreads();
        if (tt + 1 < NT) stage_buf0((tile0 + tt + 1) * 128);

        // argmax from fp32 acs (overlaps cp.async flight)
        if (tid < 128) {
            const float* ar = acsSelf + (size_t)(row0 + tid) * C_;
            float4 v0 = *(const float4*)ar;
            float4 v1 = *(const float4*)(ar + 4);
            float4 v2 = *(const float4*)(ar + 8);
            float4 v3 = *(const float4*)(ar + 12);
            float vv[16] = {v0.x,v0.y,v0.z,v0.w, v1.x,v1.y,v1.z,v1.w,
                            v2.x,v2.y,v2.z,v2.w, v3.x,v3.y,v3.z,v3.w};
            float best = vv[0]; int c = 0;
#pragma unroll
            for (int cc = 1; cc < C_; cc++)
                if (vv[cc] > best) { best = vv[cc]; c = cc; }
            cidx[tid] = c;
        }

        // ---- half 1: ks 6..10 ----
        if (tt + 1 < NT) { CPWAITG(1); } else { CPWAITG(0); }
        __syncthreads();
#pragma unroll
        for (int ks = 6; ks < 11; ks++) {
            const int k0l = (ks - 6) * 8;      // X1 local
            const int kw = ks * 8;             // Wp global
            uint32_t a[2][4], b[8][2];
#pragma unroll
            for (int mi = 0; mi < 2; mi++) {
                int r = wr + mi * 16 + g;
                a[mi][0] = X1[r * 44 + k0l + t];
                a[mi][1] = X1[(r + 8) * 44 + k0l + t];
                a[mi][2] = X1[r * 44 + k0l + t + 4];
                a[mi][3] = X1[(r + 8) * 44 + k0l + t + 4];
            }
#pragma unroll
            for (int ni = 0; ni < 8; ni++) {
                int n = wc + ni * 8 + g;
                b[ni][0] = Wp[(kw + t) * 136 + n];
                b[ni][1] = Wp[(kw + t + 4) * 136 + n];
            }
#pragma unroll
            for (int mi = 0; mi < 2; mi++)
#pragma unroll
                for (int ni = 0; ni < 8; ni++)
                    mma16(acc[mi][ni], a[mi], b[ni]);
        }
        __syncthreads();       // buf1 consumed + cidx visible
        if (tt + 1 < NT) stage_buf1((tile0 + tt + 1) * 128);

        // ---- epilogue: relu(acc+b1) . W2[:,c], 2-way N reduction ----
#pragma unroll
        for (int mi = 0; mi < 2; mi++) {
            int r0 = wr + mi * 16 + g;
            int cR0 = cidx[r0], cR1 = cidx[r0 + 8];
            float s0 = 0.f, s1 = 0.f;
#pragma unroll
            for (int ni = 0; ni < 8; ni++) {
                int col0 = wc + ni * 8 + 2 * t;
                float bb0 = smf[B1_OFF + col0], bb1 = smf[B1_OFF + col0 + 1];
                float w00 = smf[W2_OFF + col0 * 17 + cR0];
                float w01 = smf[W2_OFF + (col0 + 1) * 17 + cR0];
                float w10 = smf[W2_OFF + col0 * 17 + cR1];
                float w11 = smf[W2_OFF + (col0 + 1) * 17 + cR1];
                s0 += fmaxf(acc[mi][ni][0] + bb0, 0.f) * w00
                    + fmaxf(acc[mi][ni][1] + bb1, 0.f) * w01;
                s1 += fmaxf(acc[mi][ni][2] + bb0, 0.f) * w10
                    + fmaxf(acc[mi][ni][3] + bb1, 0.f) * w11;
            }
            s0 += __shfl_xor_sync(0xffffffffu, s0, 1);
            s0 += __shfl_xor_sync(0xffffffffu, s0, 2);
            s1 += __shfl_xor_sync(0xffffffffu, s1, 1);
            s1 += __shfl_xor_sync(0xffffffffu, s1, 2);
            if (t == 0) {
                smf[PART_OFF + wn * 128 + r0] = s0;
                smf[PART_OFF + wn * 128 + r0 + 8] = s1;
            }
        }
        __syncthreads();
        if (tid < 128) {
            float q = smf[PART_OFF + tid] + smf[PART_OFF + 128 + tid]
                    + smf[B2_OFF + cidx[tid]];
            outp[row0 + tid] = q;
        }
        __syncthreads();
    }
}

// ---------------------------------------------------------------------------
extern "C" void kernel_launch(void* const* d_in, const int* in_sizes, int n_in,
                              void* d_out, int out_size)
{
    const float* state = (const float*)d_in[0];
    const float* acs   = (const float*)d_in[1];
    const float* encW  = (const float*)d_in[2];
    const float* encb  = (const float*)d_in[3];
    const float* eW1   = (const float*)d_in[4];
    const float* eb1   = (const float*)d_in[5];
    const float* eW2   = (const float*)d_in[6];
    const float* eb2   = (const float*)d_in[7];
    const float* iW1   = (const float*)d_in[8];
    const float* ib1   = (const float*)d_in[9];
    const float* iW2   = (const float*)d_in[10];
    const float* ib2   = (const float*)d_in[11];
    float* out = (float*)d_out;

    const int B = in_sizes[0] / S_;          // 32768

    cudaFuncSetAttribute(enc_kernel,
        cudaFuncAttributeMaxDynamicSharedMemorySize, E_SMEMB);
    cudaFuncSetAttribute(critic_kernel,
        cudaFuncAttributeMaxDynamicSharedMemorySize, K_SMEMB);

    enc_kernel<<<B / 64 / NTE, 256, E_SMEMB>>>(state, encW, encb, acs, B);

    dim3 grid(B / 128 / NT, NPAIR);
    critic_kernel<<<grid, 256, K_SMEMB>>>(acs, eW1, eb1, eW2, eb2,
                                          iW1, ib1, iW2, ib2, out, B);
}

// round 10
// speedup vs baseline: 1.6248x; 1.0094x over previous
#include <cuda_runtime.h>
#include <cuda_fp16.h>
#include <cstdint>

// ---------------------------------------------------------------------------
// CentralCritic, critic GEMM on fp16 mma.sync.m16n8k16 (f32 accumulate).
// R10 = R9 with the enc-kernel mma8 call-site fix:
//   ldmatrix.x4 A-feeds, u64-interleaved W B-feeds (2.4x fewer MMA-loop
//   LDS instr), atomic 2-partial epilogue (fewer barriers), 2 CTAs/SM.
// ---------------------------------------------------------------------------

#define A_   4
#define H_   3
#define HI_  2
#define C_   16
#define S_   256
#define D_   128
#define IN_  176
#define NPAIR 20
#define NT    8      // 128-row tiles per critic CTA
#define NTE   4      // 64-row tiles per enc CTA

// enc kernel strides (floats)
#define WS_ST  136
#define XE_ST  260

// critic smem layout (u32 offsets)
#define WP_OFF   0                       // 88 k2-rows * 136 u32 = 11968
#define X0_OFF   11968                   // 128*52 u32 = 6656
#define X1_OFF   18624                   // 128*44 u32 = 5632
#define W2_OFF   24256                   // 128*17 = 2176
#define B1_OFF   26432                   // 128
#define B2_OFF   26560                   // 16
#define CIDX_OFF 26576                   // 128
#define K_SMEMB  (26704 * 4)             // 106816 B (x2 CTA <= 228KB)

// enc smem offsets (floats)
#define WSE_OFF  0
#define XSE_OFF  34816
#define BE_OFF   51456
#define E_SMEMB  (51584 * 4)

__device__ __half g_ench[32768 * D_];            // enc activations, fp16
__device__ __half g_acsh[A_ * H_ * 32768 * C_];  // acs, fp16 (GEMM operand)

__constant__ int c_loo[4][3] = {{1,2,3},{0,2,3},{0,1,3},{0,1,2}};

// ---- helpers ---------------------------------------------------------------
__device__ __forceinline__ uint32_t smem_u32(const void* p) {
    uint32_t r;
    asm("{ .reg .u64 t; cvta.to.shared.u64 t, %1; cvt.u32.u64 %0, t; }"
        : "=r"(r) : "l"(p));
    return r;
}
__device__ __forceinline__ uint32_t tf32r(float x) {
    uint32_t y; asm("cvt.rna.tf32.f32 %0, %1;" : "=r"(y) : "f"(x)); return y;
}
__device__ __forceinline__ void cpasync16(uint32_t dst, const void* src) {
    asm volatile("cp.async.cg.shared.global [%0], [%1], 16;"
                 :: "r"(dst), "l"(src));
}
#define CPCOMMIT()  asm volatile("cp.async.commit_group;" ::: "memory")
#define CPWAITG(n)  asm volatile("cp.async.wait_group %0;" :: "n"(n) : "memory")

__device__ __forceinline__ void ldsm_x4(uint32_t& r0, uint32_t& r1,
                                        uint32_t& r2, uint32_t& r3,
                                        uint32_t addr) {
    asm volatile("ldmatrix.sync.aligned.m8n8.x4.shared.b16 {%0,%1,%2,%3}, [%4];"
                 : "=r"(r0), "=r"(r1), "=r"(r2), "=r"(r3) : "r"(addr));
}

// tf32 k8 (enc kernel)
__device__ __forceinline__ void mma8(float* d, const uint32_t* a,
                                     const uint32_t* b) {
    asm volatile(
        "mma.sync.aligned.m16n8k8.row.col.f32.tf32.tf32.f32 "
        "{%0,%1,%2,%3}, {%4,%5,%6,%7}, {%8,%9}, {%0,%1,%2,%3};"
        : "+f"(d[0]), "+f"(d[1]), "+f"(d[2]), "+f"(d[3])
        : "r"(a[0]), "r"(a[1]), "r"(a[2]), "r"(a[3]), "r"(b[0]), "r"(b[1]));
}
// fp16 k16 (critic kernel)
__device__ __forceinline__ void mma16(float* d, const uint32_t* a,
                                      uint32_t b0, uint32_t b1) {
    asm volatile(
        "mma.sync.aligned.m16n8k16.row.col.f32.f16.f16.f32 "
        "{%0,%1,%2,%3}, {%4,%5,%6,%7}, {%8,%9}, {%0,%1,%2,%3};"
        : "+f"(d[0]), "+f"(d[1]), "+f"(d[2]), "+f"(d[3])
        : "r"(a[0]), "r"(a[1]), "r"(a[2]), "r"(a[3]), "r"(b0), "r"(b1));
}

// ---------------------------------------------------------------------------
// encoder: zero d_out + acs->fp16 prologue, then
//          relu(state @ encW + b) -> g_ench (fp16).
// ---------------------------------------------------------------------------
__global__ __launch_bounds__(256, 1) void enc_kernel(
    const float* __restrict__ state, const float* __restrict__ encW,
    const float* __restrict__ encb, const float* __restrict__ acs,
    float* __restrict__ outz, int B)
{
    extern __shared__ float smf[];
    const int tid = threadIdx.x, wid = tid >> 5, lane = tid & 31;
    const int g = lane >> 2, t = lane & 3;
    const int wm = wid >> 2, wn = wid & 3;
    const int wr = wm * 32, wc = wn * 32;
    const int gthr = blockIdx.x * 256 + tid;
    const int nthr = gridDim.x * 256;

    // ---- zero d_out (atomic epilogue accumulates into it) ----
    {
        const int n4 = (A_ * H_ + A_ * HI_) * B / 4;
        float4 z = make_float4(0.f, 0.f, 0.f, 0.f);
        for (int idx = gthr; idx < n4; idx += nthr)
            *(float4*)(outz + (size_t)idx * 4) = z;
    }
    // ---- acs fp32 -> fp16 (layout preserved) ----
    {
        const int n4 = A_ * H_ * B * C_ / 4;
        for (int idx = gthr; idx < n4; idx += nthr) {
            float4 v = *(const float4*)(acs + (size_t)idx * 4);
            __half2 h0 = __floats2half2_rn(v.x, v.y);
            __half2 h1 = __floats2half2_rn(v.z, v.w);
            uint2 o; o.x = *(uint32_t*)&h0; o.y = *(uint32_t*)&h1;
            *(uint2*)(g_acsh + (size_t)idx * 4) = o;
        }
    }

    for (int it = 0; it < 32; it++) {
        int fi = it * 256 + tid;
        int k = fi >> 5, n4 = fi & 31;
        float4 v = *(const float4*)(encW + (size_t)k * D_ + n4 * 4);
        uint4 w; w.x = tf32r(v.x); w.y = tf32r(v.y);
        w.z = tf32r(v.z); w.w = tf32r(v.w);
        *(uint4*)(smf + WSE_OFF + k * WS_ST + n4 * 4) = w;
    }
    if (tid < D_) smf[BE_OFF + tid] = encb[tid];

    const uint32_t xbase = smem_u32(smf + XSE_OFF);
    const int tile0 = blockIdx.x * NTE;

    {
        int row0 = tile0 * 64;
        for (int it = 0; it < 16; it++) {
            int idx = it * 256 + tid;
            int c = idx & 63, row = idx >> 6;
            cpasync16(xbase + (uint32_t)(row * XE_ST + c * 4) * 4,
                      state + (size_t)(row0 + row) * S_ + c * 4);
        }
        CPCOMMIT();
    }
    CPWAITG(0);
    __syncthreads();

    for (int tt = 0; tt < NTE; tt++) {
        const int row0 = (tile0 + tt) * 64;
        float acc[2][4][4];
#pragma unroll
        for (int mi = 0; mi < 2; mi++)
#pragma unroll
            for (int ni = 0; ni < 4; ni++)
#pragma unroll
                for (int e = 0; e < 4; e++) acc[mi][ni][e] = 0.f;

        const uint32_t* Xu = (const uint32_t*)(smf + XSE_OFF);
        const uint32_t* Wu = (const uint32_t*)(smf + WSE_OFF);
#pragma unroll
        for (int ks = 0; ks < 32; ks++) {
            const int k0 = ks * 8;
            uint32_t a[2][4], b[4][2];
#pragma unroll
            for (int mi = 0; mi < 2; mi++) {
                int r = wr + mi * 16 + g;
                a[mi][0] = Xu[r * XE_ST + k0 + t];
                a[mi][1] = Xu[(r + 8) * XE_ST + k0 + t];
                a[mi][2] = Xu[r * XE_ST + k0 + t + 4];
                a[mi][3] = Xu[(r + 8) * XE_ST + k0 + t + 4];
            }
#pragma unroll
            for (int ni = 0; ni < 4; ni++) {
                int n = wc + ni * 8 + g;
                b[ni][0] = Wu[(k0 + t) * WS_ST + n];
                b[ni][1] = Wu[(k0 + t + 4) * WS_ST + n];
            }
#pragma unroll
            for (int mi = 0; mi < 2; mi++)
#pragma unroll
                for (int ni = 0; ni < 4; ni++)
                    mma8(acc[mi][ni], a[mi], b[ni]);
        }
        __syncthreads();

        if (tt + 1 < NTE) {
            int nrow0 = (tile0 + tt + 1) * 64;
            for (int it = 0; it < 16; it++) {
                int idx = it * 256 + tid;
                int c = idx & 63, row = idx >> 6;
                cpasync16(xbase + (uint32_t)(row * XE_ST + c * 4) * 4,
                          state + (size_t)(nrow0 + row) * S_ + c * 4);
            }
            CPCOMMIT();
        }

        // epilogue: bias + relu -> fp16 pairs
#pragma unroll
        for (int mi = 0; mi < 2; mi++) {
            int r0 = row0 + wr + mi * 16 + g;
#pragma unroll
            for (int ni = 0; ni < 4; ni++) {
                int col = wc + ni * 8 + 2 * t;
                float b0 = smf[BE_OFF + col], b1v = smf[BE_OFF + col + 1];
                __half2 h0 = __floats2half2_rn(
                    fmaxf(acc[mi][ni][0] + b0, 0.f),
                    fmaxf(acc[mi][ni][1] + b1v, 0.f));
                __half2 h1 = __floats2half2_rn(
                    fmaxf(acc[mi][ni][2] + b0, 0.f),
                    fmaxf(acc[mi][ni][3] + b1v, 0.f));
                *(__half2*)(g_ench + (size_t)r0 * D_ + col) = h0;
                *(__half2*)(g_ench + (size_t)(r0 + 8) * D_ + col) = h1;
            }
        }

        if (tt + 1 < NTE) CPWAITG(0);
        __syncthreads();
    }
}

// ---------------------------------------------------------------------------
// critic: 256 thr, 8 warps (4 wm x 2 wn), warp tile 32x64, fp16 m16n8k16,
// 2 CTAs/SM, ldmatrix A-feeds, u64-interleaved W, atomic epilogue.
// ---------------------------------------------------------------------------
__global__ __launch_bounds__(256, 2) void critic_kernel(
    const float* __restrict__ acs,
    const float* __restrict__ eW1, const float* __restrict__ eb1,
    const float* __restrict__ eW2, const float* __restrict__ eb2,
    const float* __restrict__ iW1, const float* __restrict__ ib1,
    const float* __restrict__ iW2, const float* __restrict__ ib2,
    float* __restrict__ out, int B)
{
    extern __shared__ float smf[];
    const int tid = threadIdx.x, wid = tid >> 5, lane = tid & 31;
    const int g = lane >> 2, t = lane & 3;
    const int wm = wid >> 1, wn = wid & 1;
    const int wr = wm * 32, wc = wn * 64;
    const int p = blockIdx.y;

    int i, head;
    const float *W1, *b1, *W2, *b2;
    float* outp;
    if (p < A_ * H_) {
        i = p / H_; int j = p % H_; head = j;
        W1 = eW1 + (size_t)(j * A_ + i) * IN_ * D_;
        b1 = eb1 + (size_t)(j * A_ + i) * D_;
        W2 = eW2 + (size_t)(j * A_ + i) * D_ * C_;
        b2 = eb2 + (size_t)(j * A_ + i) * C_;
        outp = out + (size_t)p * B;
    } else {
        int q = p - A_ * H_;
        i = q / HI_; int j = q % HI_; head = j + 1;
        W1 = iW1 + (size_t)(j * A_ + i) * IN_ * D_;
        b1 = ib1 + (size_t)(j * A_ + i) * D_;
        W2 = iW2 + (size_t)(j * A_ + i) * D_ * C_;
        b2 = ib2 + (size_t)(j * A_ + i) * C_;
        outp = out + (size_t)(A_ * H_) * B + (size_t)q * B;
    }
    const __half* acsA[3];
    acsA[0] = g_acsh + (size_t)(c_loo[i][0] * H_ + head) * B * C_;
    acsA[1] = g_acsh + (size_t)(c_loo[i][1] * H_ + head) * B * C_;
    acsA[2] = g_acsh + (size_t)(c_loo[i][2] * H_ + head) * B * C_;
    const float* acsSelf = acs + (size_t)(i * H_ + head) * B * C_;

    // ---- stage W1 fp16, (n, n+8)-interleaved u64 rows, k-pairs in u32 ----
    // fp16 idx = (k>>1)*272 + (n>>4)*32 + (n&7)*4 + ((n>>3)&1)*2 + (k&1)
    __half* Wph = (__half*)(smf + WP_OFF);
    for (int it = 0; it < 22; it++) {
        int fi = it * 256 + tid;            // 5632 float4
        int k = fi >> 5, n0 = (fi & 31) * 4;
        float4 v = *(const float4*)(W1 + (size_t)k * D_ + n0);
        int base = (k >> 1) * 272 + (n0 >> 4) * 32 + ((n0 >> 3) & 1) * 2
                 + (k & 1) + (n0 & 7) * 4;
        Wph[base + 0]  = __float2half_rn(v.x);
        Wph[base + 4]  = __float2half_rn(v.y);
        Wph[base + 8]  = __float2half_rn(v.z);
        Wph[base + 12] = __float2half_rn(v.w);
    }
    for (int it = 0; it < 8; it++) {
        int idx = it * 256 + tid;           // 2048 floats
        int d = idx >> 4, c = idx & 15;
        smf[W2_OFF + d * 17 + c] = W2[idx];
    }
    if (tid < D_) smf[B1_OFF + tid] = b1[tid];
    if (tid < C_) smf[B2_OFF + tid] = b2[tid];

    const uint32_t x0b = smem_u32(smf + X0_OFF);
    const uint32_t x1b = smem_u32(smf + X1_OFF);
    const int tile0 = blockIdx.x * NT;
    int* cidx = (int*)(smf + CIDX_OFF);

    // buf0: 12 chunks/row (acs 6 + enc[0..47] 6), 1536 chunks, 6 iters
    auto stage_buf0 = [&](int row0) {
#pragma unroll
        for (int it = 0; it < 6; it++) {
            int idx = it * 256 + tid;
            int row = idx / 12, c = idx - (idx / 12) * 12;
            const void* src;
            if (c < 6)
                src = acsA[c >> 1] + (size_t)(row0 + row) * C_ + (c & 1) * 8;
            else
                src = g_ench + (size_t)(row0 + row) * D_ + (c - 6) * 8;
            cpasync16(x0b + (uint32_t)(row * 52 + c * 4) * 4, src);
        }
        CPCOMMIT();
    };
    // buf1: enc[48..127], 10 chunks/row, 1280 chunks, 5 iters
    auto stage_buf1 = [&](int row0) {
#pragma unroll
        for (int it = 0; it < 5; it++) {
            int idx = it * 256 + tid;
            int row = idx / 10, u = idx - (idx / 10) * 10;
            const void* src = g_ench + (size_t)(row0 + row) * D_ + 48 + u * 8;
            cpasync16(x1b + (uint32_t)(row * 44 + u * 4) * 4, src);
        }
        CPCOMMIT();
    };

    stage_buf0(tile0 * 128);
    stage_buf1(tile0 * 128);

    const uint2* Wq = (const uint2*)(smf + WP_OFF);    // u64 view
    const int nb = (wc >> 4) * 8 + g;                  // u64 col base

    // ldmatrix lane addressing (A fragments)
    const int lrow = ((lane >> 3) & 1) * 8 + (lane & 7);
    const uint32_t lk16 = (uint32_t)(lane >> 4) * 16;  // byte offset for k8-15
    const uint32_t aX0base = x0b + (uint32_t)((wr + lrow) * 208) + lk16;
    const uint32_t aX1base = x1b + (uint32_t)((wr + lrow) * 176) + lk16;

    for (int tt = 0; tt < NT; tt++) {
        const int row0 = (tile0 + tt) * 128;
        float acc[2][8][4];
#pragma unroll
        for (int mi = 0; mi < 2; mi++)
#pragma unroll
            for (int ni = 0; ni < 8; ni++)
#pragma unroll
                for (int e = 0; e < 4; e++) acc[mi][ni][e] = 0.f;

        // ---- half 0: ks 0..5 ----
        CPWAITG(1);
        __syncthreads();
#pragma unroll
        for (int ks = 0; ks < 6; ks++) {
            uint32_t a[2][4];
            ldsm_x4(a[0][0], a[0][1], a[0][2], a[0][3], aX0base + ks * 32);
            ldsm_x4(a[1][0], a[1][1], a[1][2], a[1][3],
                    aX0base + 16 * 208 + ks * 32);
            const int kr0 = (ks * 8 + t) * 68 + nb;
            uint2 c0[4], c1[4];
#pragma unroll
            for (int j = 0; j < 4; j++) {
                c0[j] = Wq[kr0 + j * 8];
                c1[j] = Wq[kr0 + 4 * 68 + j * 8];
            }
#pragma unroll
            for (int mi = 0; mi < 2; mi++)
#pragma unroll
                for (int j = 0; j < 4; j++) {
                    mma16(acc[mi][2 * j],     a[mi], c0[j].x, c1[j].x);
                    mma16(acc[mi][2 * j + 1], a[mi], c0[j].y, c1[j].y);
                }
        }
        __syncthreads();
        if (tt + 1 < NT) stage_buf0((tile0 + tt + 1) * 128);

        // argmax from fp32 acs (overlaps cp.async flight)
        if (tid < 128) {
            const float* ar = acsSelf + (size_t)(row0 + tid) * C_;
            float4 v0 = *(const float4*)ar;
            float4 v1 = *(const float4*)(ar + 4);
            float4 v2 = *(const float4*)(ar + 8);
            float4 v3 = *(const float4*)(ar + 12);
            float vv[16] = {v0.x,v0.y,v0.z,v0.w, v1.x,v1.y,v1.z,v1.w,
                            v2.x,v2.y,v2.z,v2.w, v3.x,v3.y,v3.z,v3.w};
            float best = vv[0]; int c = 0;
#pragma unroll
            for (int cc = 1; cc < C_; cc++)
                if (vv[cc] > best) { best = vv[cc]; c = cc; }
            cidx[tid] = c;
        }

        // ---- half 1: ks 6..10 ----
        if (tt + 1 < NT) { CPWAITG(1); } else { CPWAITG(0); }
        __syncthreads();
#pragma unroll
        for (int ks = 6; ks < 11; ks++) {
            uint32_t a[2][4];
            ldsm_x4(a[0][0], a[0][1], a[0][2], a[0][3],
                    aX1base + (ks - 6) * 32);
            ldsm_x4(a[1][0], a[1][1], a[1][2], a[1][3],
                    aX1base + 16 * 176 + (ks - 6) * 32);
            const int kr0 = (ks * 8 + t) * 68 + nb;
            uint2 c0[4], c1[4];
#pragma unroll
            for (int j = 0; j < 4; j++) {
                c0[j] = Wq[kr0 + j * 8];
                c1[j] = Wq[kr0 + 4 * 68 + j * 8];
            }
#pragma unroll
            for (int mi = 0; mi < 2; mi++)
#pragma unroll
                for (int j = 0; j < 4; j++) {
                    mma16(acc[mi][2 * j],     a[mi], c0[j].x, c1[j].x);
                    mma16(acc[mi][2 * j + 1], a[mi], c0[j].y, c1[j].y);
                }
        }
        __syncthreads();       // buf1 consumed + cidx visible
        if (tt + 1 < NT) stage_buf1((tile0 + tt + 1) * 128);

        // ---- epilogue: relu(acc+b1) . W2[:,c]; two commutative atomics ----
#pragma unroll
        for (int mi = 0; mi < 2; mi++) {
            int r0 = wr + mi * 16 + g;
            int cR0 = cidx[r0], cR1 = cidx[r0 + 8];
            float s0 = 0.f, s1 = 0.f;
#pragma unroll
            for (int ni = 0; ni < 8; ni++) {
                int col0 = wc + ni * 8 + 2 * t;
                float bb0 = smf[B1_OFF + col0], bb1 = smf[B1_OFF + col0 + 1];
                float w00 = smf[W2_OFF + col0 * 17 + cR0];
                float w01 = smf[W2_OFF + (col0 + 1) * 17 + cR0];
                float w10 = smf[W2_OFF + col0 * 17 + cR1];
                float w11 = smf[W2_OFF + (col0 + 1) * 17 + cR1];
                s0 += fmaxf(acc[mi][ni][0] + bb0, 0.f) * w00
                    + fmaxf(acc[mi][ni][1] + bb1, 0.f) * w01;
                s1 += fmaxf(acc[mi][ni][2] + bb0, 0.f) * w10
                    + fmaxf(acc[mi][ni][3] + bb1, 0.f) * w11;
            }
            s0 += __shfl_xor_sync(0xffffffffu, s0, 1);
            s0 += __shfl_xor_sync(0xffffffffu, s0, 2);
            s1 += __shfl_xor_sync(0xffffffffu, s1, 1);
            s1 += __shfl_xor_sync(0xffffffffu, s1, 2);
            if (t == 0) {
                if (wn == 0) { s0 += smf[B2_OFF + cR0]; s1 += smf[B2_OFF + cR1]; }
                atomicAdd(&outp[row0 + r0], s0);
                atomicAdd(&outp[row0 + r0 + 8], s1);
            }
        }
        // no trailing sync: cidx next written after half0 sync of tile tt+1
    }
}

// ---------------------------------------------------------------------------
extern "C" void kernel_launch(void* const* d_in, const int* in_sizes, int n_in,
                              void* d_out, int out_size)
{
    const float* state = (const float*)d_in[0];
    const float* acs   = (const float*)d_in[1];
    const float* encW  = (const float*)d_in[2];
    const float* encb  = (const float*)d_in[3];
    const float* eW1   = (const float*)d_in[4];
    const float* eb1   = (const float*)d_in[5];
    const float* eW2   = (const float*)d_in[6];
    const float* eb2   = (const float*)d_in[7];
    const float* iW1   = (const float*)d_in[8];
    const float* ib1   = (const float*)d_in[9];
    const float* iW2   = (const float*)d_in[10];
    const float* ib2   = (const float*)d_in[11];
    float* out = (float*)d_out;

    const int B = in_sizes[0] / S_;          // 32768

    cudaFuncSetAttribute(enc_kernel,
        cudaFuncAttributeMaxDynamicSharedMemorySize, E_SMEMB);
    cudaFuncSetAttribute(critic_kernel,
        cudaFuncAttributeMaxDynamicSharedMemorySize, K_SMEMB);

    enc_kernel<<<B / 64 / NTE, 256, E_SMEMB>>>(state, encW, encb, acs, out, B);

    dim3 grid(B / 128 / NT, NPAIR);
    critic_kernel<<<grid, 256, K_SMEMB>>>(acs, eW1, eb1, eW2, eb2,
                                          iW1, ib1, iW2, ib2, out, B);
}

// round 11
// speedup vs baseline: 1.8669x; 1.1490x over previous
#include <cuda_runtime.h>
#include <cuda_fp16.h>
#include <cstdint>

// ---------------------------------------------------------------------------
// CentralCritic, critic GEMM on fp16 mma.sync.m16n8k16 (f32 accumulate).
// R11 = R10 inner loop + balanced persistent partition:
//   592 CTAs (2 full waves on 148/152 SMs), each statically owns one
//   (agent,head) pair and a contiguous 8-9 tile range. Fixes the 72%
//   wave-quantization loss of the old (32,20) grid.
// ---------------------------------------------------------------------------

#define A_   4
#define H_   3
#define HI_  2
#define C_   16
#define S_   256
#define D_   128
#define IN_  176
#define NPAIR 20
#define NCTA  592    // critic CTAs: 2 waves on 148 SMs (2 CTAs/SM)
#define NTE   4      // 64-row tiles per enc CTA

// enc kernel strides (floats)
#define WS_ST  136
#define XE_ST  260

// critic smem layout (u32 offsets)
#define WP_OFF   0                       // 88 k2-rows * 136 u32 = 11968
#define X0_OFF   11968                   // 128*52 u32 = 6656
#define X1_OFF   18624                   // 128*44 u32 = 5632
#define W2_OFF   24256                   // 128*17 = 2176
#define B1_OFF   26432                   // 128
#define B2_OFF   26560                   // 16
#define CIDX_OFF 26576                   // 128
#define K_SMEMB  (26704 * 4)             // 106816 B (x2 CTA <= 228KB)

// enc smem offsets (floats)
#define WSE_OFF  0
#define XSE_OFF  34816
#define BE_OFF   51456
#define E_SMEMB  (51584 * 4)

__device__ __half g_ench[32768 * D_];            // enc activations, fp16
__device__ __half g_acsh[A_ * H_ * 32768 * C_];  // acs, fp16 (GEMM operand)

__constant__ int c_loo[4][3] = {{1,2,3},{0,2,3},{0,1,3},{0,1,2}};

// ---- helpers ---------------------------------------------------------------
__device__ __forceinline__ uint32_t smem_u32(const void* p) {
    uint32_t r;
    asm("{ .reg .u64 t; cvta.to.shared.u64 t, %1; cvt.u32.u64 %0, t; }"
        : "=r"(r) : "l"(p));
    return r;
}
__device__ __forceinline__ uint32_t tf32r(float x) {
    uint32_t y; asm("cvt.rna.tf32.f32 %0, %1;" : "=r"(y) : "f"(x)); return y;
}
__device__ __forceinline__ void cpasync16(uint32_t dst, const void* src) {
    asm volatile("cp.async.cg.shared.global [%0], [%1], 16;"
                 :: "r"(dst), "l"(src));
}
#define CPCOMMIT()  asm volatile("cp.async.commit_group;" ::: "memory")
#define CPWAITG(n)  asm volatile("cp.async.wait_group %0;" :: "n"(n) : "memory")

__device__ __forceinline__ void ldsm_x4(uint32_t& r0, uint32_t& r1,
                                        uint32_t& r2, uint32_t& r3,
                                        uint32_t addr) {
    asm volatile("ldmatrix.sync.aligned.m8n8.x4.shared.b16 {%0,%1,%2,%3}, [%4];"
                 : "=r"(r0), "=r"(r1), "=r"(r2), "=r"(r3) : "r"(addr));
}

// tf32 k8 (enc kernel)
__device__ __forceinline__ void mma8(float* d, const uint32_t* a,
                                     const uint32_t* b) {
    asm volatile(
        "mma.sync.aligned.m16n8k8.row.col.f32.tf32.tf32.f32 "
        "{%0,%1,%2,%3}, {%4,%5,%6,%7}, {%8,%9}, {%0,%1,%2,%3};"
        : "+f"(d[0]), "+f"(d[1]), "+f"(d[2]), "+f"(d[3])
        : "r"(a[0]), "r"(a[1]), "r"(a[2]), "r"(a[3]), "r"(b[0]), "r"(b[1]));
}
// fp16 k16 (critic kernel)
__device__ __forceinline__ void mma16(float* d, const uint32_t* a,
                                      uint32_t b0, uint32_t b1) {
    asm volatile(
        "mma.sync.aligned.m16n8k16.row.col.f32.f16.f16.f32 "
        "{%0,%1,%2,%3}, {%4,%5,%6,%7}, {%8,%9}, {%0,%1,%2,%3};"
        : "+f"(d[0]), "+f"(d[1]), "+f"(d[2]), "+f"(d[3])
        : "r"(a[0]), "r"(a[1]), "r"(a[2]), "r"(a[3]), "r"(b0), "r"(b1));
}

// ---------------------------------------------------------------------------
// encoder: zero d_out + acs->fp16 prologue, then
//          relu(state @ encW + b) -> g_ench (fp16).
// ---------------------------------------------------------------------------
__global__ __launch_bounds__(256, 1) void enc_kernel(
    const float* __restrict__ state, const float* __restrict__ encW,
    const float* __restrict__ encb, const float* __restrict__ acs,
    float* __restrict__ outz, int B)
{
    extern __shared__ float smf[];
    const int tid = threadIdx.x, wid = tid >> 5, lane = tid & 31;
    const int g = lane >> 2, t = lane & 3;
    const int wm = wid >> 2, wn = wid & 3;
    const int wr = wm * 32, wc = wn * 32;
    const int gthr = blockIdx.x * 256 + tid;
    const int nthr = gridDim.x * 256;

    // ---- zero d_out (atomic epilogue accumulates into it) ----
    {
        const int n4 = (A_ * H_ + A_ * HI_) * B / 4;
        float4 z = make_float4(0.f, 0.f, 0.f, 0.f);
        for (int idx = gthr; idx < n4; idx += nthr)
            *(float4*)(outz + (size_t)idx * 4) = z;
    }
    // ---- acs fp32 -> fp16 (layout preserved) ----
    {
        const int n4 = A_ * H_ * B * C_ / 4;
        for (int idx = gthr; idx < n4; idx += nthr) {
            float4 v = *(const float4*)(acs + (size_t)idx * 4);
            __half2 h0 = __floats2half2_rn(v.x, v.y);
            __half2 h1 = __floats2half2_rn(v.z, v.w);
            uint2 o; o.x = *(uint32_t*)&h0; o.y = *(uint32_t*)&h1;
            *(uint2*)(g_acsh + (size_t)idx * 4) = o;
        }
    }

    for (int it = 0; it < 32; it++) {
        int fi = it * 256 + tid;
        int k = fi >> 5, n4 = fi & 31;
        float4 v = *(const float4*)(encW + (size_t)k * D_ + n4 * 4);
        uint4 w; w.x = tf32r(v.x); w.y = tf32r(v.y);
        w.z = tf32r(v.z); w.w = tf32r(v.w);
        *(uint4*)(smf + WSE_OFF + k * WS_ST + n4 * 4) = w;
    }
    if (tid < D_) smf[BE_OFF + tid] = encb[tid];

    const uint32_t xbase = smem_u32(smf + XSE_OFF);
    const int tile0 = blockIdx.x * NTE;

    {
        int row0 = tile0 * 64;
        for (int it = 0; it < 16; it++) {
            int idx = it * 256 + tid;
            int c = idx & 63, row = idx >> 6;
            cpasync16(xbase + (uint32_t)(row * XE_ST + c * 4) * 4,
                      state + (size_t)(row0 + row) * S_ + c * 4);
        }
        CPCOMMIT();
    }
    CPWAITG(0);
    __syncthreads();

    for (int tt = 0; tt < NTE; tt++) {
        const int row0 = (tile0 + tt) * 64;
        float acc[2][4][4];
#pragma unroll
        for (int mi = 0; mi < 2; mi++)
#pragma unroll
            for (int ni = 0; ni < 4; ni++)
#pragma unroll
                for (int e = 0; e < 4; e++) acc[mi][ni][e] = 0.f;

        const uint32_t* Xu = (const uint32_t*)(smf + XSE_OFF);
        const uint32_t* Wu = (const uint32_t*)(smf + WSE_OFF);
#pragma unroll
        for (int ks = 0; ks < 32; ks++) {
            const int k0 = ks * 8;
            uint32_t a[2][4], b[4][2];
#pragma unroll
            for (int mi = 0; mi < 2; mi++) {
                int r = wr + mi * 16 + g;
                a[mi][0] = Xu[r * XE_ST + k0 + t];
                a[mi][1] = Xu[(r + 8) * XE_ST + k0 + t];
                a[mi][2] = Xu[r * XE_ST + k0 + t + 4];
                a[mi][3] = Xu[(r + 8) * XE_ST + k0 + t + 4];
            }
#pragma unroll
            for (int ni = 0; ni < 4; ni++) {
                int n = wc + ni * 8 + g;
                b[ni][0] = Wu[(k0 + t) * WS_ST + n];
                b[ni][1] = Wu[(k0 + t + 4) * WS_ST + n];
            }
#pragma unroll
            for (int mi = 0; mi < 2; mi++)
#pragma unroll
                for (int ni = 0; ni < 4; ni++)
                    mma8(acc[mi][ni], a[mi], b[ni]);
        }
        __syncthreads();

        if (tt + 1 < NTE) {
            int nrow0 = (tile0 + tt + 1) * 64;
            for (int it = 0; it < 16; it++) {
                int idx = it * 256 + tid;
                int c = idx & 63, row = idx >> 6;
                cpasync16(xbase + (uint32_t)(row * XE_ST + c * 4) * 4,
                          state + (size_t)(nrow0 + row) * S_ + c * 4);
            }
            CPCOMMIT();
        }

        // epilogue: bias + relu -> fp16 pairs
#pragma unroll
        for (int mi = 0; mi < 2; mi++) {
            int r0 = row0 + wr + mi * 16 + g;
#pragma unroll
            for (int ni = 0; ni < 4; ni++) {
                int col = wc + ni * 8 + 2 * t;
                float b0 = smf[BE_OFF + col], b1v = smf[BE_OFF + col + 1];
                __half2 h0 = __floats2half2_rn(
                    fmaxf(acc[mi][ni][0] + b0, 0.f),
                    fmaxf(acc[mi][ni][1] + b1v, 0.f));
                __half2 h1 = __floats2half2_rn(
                    fmaxf(acc[mi][ni][2] + b0, 0.f),
                    fmaxf(acc[mi][ni][3] + b1v, 0.f));
                *(__half2*)(g_ench + (size_t)r0 * D_ + col) = h0;
                *(__half2*)(g_ench + (size_t)(r0 + 8) * D_ + col) = h1;
            }
        }

        if (tt + 1 < NTE) CPWAITG(0);
        __syncthreads();
    }
}

// ---------------------------------------------------------------------------
// critic: 256 thr, 8 warps (4 wm x 2 wn), warp tile 32x64, fp16 m16n8k16,
// 2 CTAs/SM, ldmatrix A-feeds, u64-interleaved W, atomic epilogue.
// Balanced static partition: CTA c -> pair p = floor(5c/148), tile range
// [l*T/cnt, (l+1)*T/cnt) within that pair.
// ---------------------------------------------------------------------------
__global__ __launch_bounds__(256, 2) void critic_kernel(
    const float* __restrict__ acs,
    const float* __restrict__ eW1, const float* __restrict__ eb1,
    const float* __restrict__ eW2, const float* __restrict__ eb2,
    const float* __restrict__ iW1, const float* __restrict__ ib1,
    const float* __restrict__ iW2, const float* __restrict__ ib2,
    float* __restrict__ out, int B)
{
    extern __shared__ float smf[];
    const int tid = threadIdx.x, wid = tid >> 5, lane = tid & 31;
    const int g = lane >> 2, t = lane & 3;
    const int wm = wid >> 1, wn = wid & 1;
    const int wr = wm * 32, wc = wn * 64;

    // ---- balanced partition ----
    const int cb = blockIdx.x;                     // 0..NCTA-1
    const int p  = (cb * 5) / 148;                 // = cb*NPAIR/NCTA
    const int c0 = (148 * p + 4) / 5;              // first CTA of pair p
    const int c1 = (148 * (p + 1) + 4) / 5;        // first CTA of pair p+1
    const int cnt = c1 - c0;
    const int l = cb - c0;
    const int tilesT = B / 128;
    const int tb = (l * tilesT) / cnt;
    const int te = ((l + 1) * tilesT) / cnt;

    int i, head;
    const float *W1, *b1, *W2, *b2;
    float* outp;
    if (p < A_ * H_) {
        i = p / H_; int j = p % H_; head = j;
        W1 = eW1 + (size_t)(j * A_ + i) * IN_ * D_;
        b1 = eb1 + (size_t)(j * A_ + i) * D_;
        W2 = eW2 + (size_t)(j * A_ + i) * D_ * C_;
        b2 = eb2 + (size_t)(j * A_ + i) * C_;
        outp = out + (size_t)p * B;
    } else {
        int q = p - A_ * H_;
        i = q / HI_; int j = q % HI_; head = j + 1;
        W1 = iW1 + (size_t)(j * A_ + i) * IN_ * D_;
        b1 = ib1 + (size_t)(j * A_ + i) * D_;
        W2 = iW2 + (size_t)(j * A_ + i) * D_ * C_;
        b2 = ib2 + (size_t)(j * A_ + i) * C_;
        outp = out + (size_t)(A_ * H_) * B + (size_t)q * B;
    }
    const __half* acsA[3];
    acsA[0] = g_acsh + (size_t)(c_loo[i][0] * H_ + head) * B * C_;
    acsA[1] = g_acsh + (size_t)(c_loo[i][1] * H_ + head) * B * C_;
    acsA[2] = g_acsh + (size_t)(c_loo[i][2] * H_ + head) * B * C_;
    const float* acsSelf = acs + (size_t)(i * H_ + head) * B * C_;

    // ---- stage W1 fp16, (n, n+8)-interleaved u64 rows, k-pairs in u32 ----
    __half* Wph = (__half*)(smf + WP_OFF);
    for (int it = 0; it < 22; it++) {
        int fi = it * 256 + tid;            // 5632 float4
        int k = fi >> 5, n0 = (fi & 31) * 4;
        float4 v = *(const float4*)(W1 + (size_t)k * D_ + n0);
        int base = (k >> 1) * 272 + (n0 >> 4) * 32 + ((n0 >> 3) & 1) * 2
                 + (k & 1) + (n0 & 7) * 4;
        Wph[base + 0]  = __float2half_rn(v.x);
        Wph[base + 4]  = __float2half_rn(v.y);
        Wph[base + 8]  = __float2half_rn(v.z);
        Wph[base + 12] = __float2half_rn(v.w);
    }
    for (int it = 0; it < 8; it++) {
        int idx = it * 256 + tid;           // 2048 floats
        int d = idx >> 4, c = idx & 15;
        smf[W2_OFF + d * 17 + c] = W2[idx];
    }
    if (tid < D_) smf[B1_OFF + tid] = b1[tid];
    if (tid < C_) smf[B2_OFF + tid] = b2[tid];

    const uint32_t x0b = smem_u32(smf + X0_OFF);
    const uint32_t x1b = smem_u32(smf + X1_OFF);
    int* cidx = (int*)(smf + CIDX_OFF);

    // buf0: 12 chunks/row (acs 6 + enc[0..47] 6), 1536 chunks, 6 iters
    auto stage_buf0 = [&](int row0) {
#pragma unroll
        for (int it = 0; it < 6; it++) {
            int idx = it * 256 + tid;
            int row = idx / 12, c = idx - (idx / 12) * 12;
            const void* src;
            if (c < 6)
                src = acsA[c >> 1] + (size_t)(row0 + row) * C_ + (c & 1) * 8;
            else
                src = g_ench + (size_t)(row0 + row) * D_ + (c - 6) * 8;
            cpasync16(x0b + (uint32_t)(row * 52 + c * 4) * 4, src);
        }
        CPCOMMIT();
    };
    // buf1: enc[48..127], 10 chunks/row, 1280 chunks, 5 iters
    auto stage_buf1 = [&](int row0) {
#pragma unroll
        for (int it = 0; it < 5; it++) {
            int idx = it * 256 + tid;
            int row = idx / 10, u = idx - (idx / 10) * 10;
            const void* src = g_ench + (size_t)(row0 + row) * D_ + 48 + u * 8;
            cpasync16(x1b + (uint32_t)(row * 44 + u * 4) * 4, src);
        }
        CPCOMMIT();
    };

    stage_buf0(tb * 128);
    stage_buf1(tb * 128);

    const uint2* Wq = (const uint2*)(smf + WP_OFF);    // u64 view
    const int nb = (wc >> 4) * 8 + g;                  // u64 col base

    // ldmatrix lane addressing (A fragments)
    const int lrow = ((lane >> 3) & 1) * 8 + (lane & 7);
    const uint32_t lk16 = (uint32_t)(lane >> 4) * 16;  // byte offset for k8-15
    const uint32_t aX0base = x0b + (uint32_t)((wr + lrow) * 208) + lk16;
    const uint32_t aX1base = x1b + (uint32_t)((wr + lrow) * 176) + lk16;

    for (int tt = tb; tt < te; tt++) {
        const int row0 = tt * 128;
        const bool hasNext = (tt + 1 < te);
        float acc[2][8][4];
#pragma unroll
        for (int mi = 0; mi < 2; mi++)
#pragma unroll
            for (int ni = 0; ni < 8; ni++)
#pragma unroll
                for (int e = 0; e < 4; e++) acc[mi][ni][e] = 0.f;

        // ---- half 0: ks 0..5 ----
        CPWAITG(1);
        __syncthreads();
#pragma unroll
        for (int ks = 0; ks < 6; ks++) {
            uint32_t a[2][4];
            ldsm_x4(a[0][0], a[0][1], a[0][2], a[0][3], aX0base + ks * 32);
            ldsm_x4(a[1][0], a[1][1], a[1][2], a[1][3],
                    aX0base + 16 * 208 + ks * 32);
            const int kr0 = (ks * 8 + t) * 68 + nb;
            uint2 c0v[4], c1v[4];
#pragma unroll
            for (int j = 0; j < 4; j++) {
                c0v[j] = Wq[kr0 + j * 8];
                c1v[j] = Wq[kr0 + 4 * 68 + j * 8];
            }
#pragma unroll
            for (int mi = 0; mi < 2; mi++)
#pragma unroll
                for (int j = 0; j < 4; j++) {
                    mma16(acc[mi][2 * j],     a[mi], c0v[j].x, c1v[j].x);
                    mma16(acc[mi][2 * j + 1], a[mi], c0v[j].y, c1v[j].y);
                }
        }
        __syncthreads();
        if (hasNext) stage_buf0((tt + 1) * 128);

        // argmax from fp32 acs (overlaps cp.async flight)
        if (tid < 128) {
            const float* ar = acsSelf + (size_t)(row0 + tid) * C_;
            float4 v0 = *(const float4*)ar;
            float4 v1 = *(const float4*)(ar + 4);
            float4 v2 = *(const float4*)(ar + 8);
            float4 v3 = *(const float4*)(ar + 12);
            float vv[16] = {v0.x,v0.y,v0.z,v0.w, v1.x,v1.y,v1.z,v1.w,
                            v2.x,v2.y,v2.z,v2.w, v3.x,v3.y,v3.z,v3.w};
            float best = vv[0]; int c = 0;
#pragma unroll
            for (int cc = 1; cc < C_; cc++)
                if (vv[cc] > best) { best = vv[cc]; c = cc; }
            cidx[tid] = c;
        }

        // ---- half 1: ks 6..10 ----
        if (hasNext) { CPWAITG(1); } else { CPWAITG(0); }
        __syncthreads();
#pragma unroll
        for (int ks = 6; ks < 11; ks++) {
            uint32_t a[2][4];
            ldsm_x4(a[0][0], a[0][1], a[0][2], a[0][3],
                    aX1base + (ks - 6) * 32);
            ldsm_x4(a[1][0], a[1][1], a[1][2], a[1][3],
                    aX1base + 16 * 176 + (ks - 6) * 32);
            const int kr0 = (ks * 8 + t) * 68 + nb;
            uint2 c0v[4], c1v[4];
#pragma unroll
            for (int j = 0; j < 4; j++) {
                c0v[j] = Wq[kr0 + j * 8];
                c1v[j] = Wq[kr0 + 4 * 68 + j * 8];
            }
#pragma unroll
            for (int mi = 0; mi < 2; mi++)
#pragma unroll
                for (int j = 0; j < 4; j++) {
                    mma16(acc[mi][2 * j],     a[mi], c0v[j].x, c1v[j].x);
                    mma16(acc[mi][2 * j + 1], a[mi], c0v[j].y, c1v[j].y);
                }
        }
        __syncthreads();       // buf1 consumed + cidx visible
        if (hasNext) stage_buf1((tt + 1) * 128);

        // ---- epilogue: relu(acc+b1) . W2[:,c]; two commutative atomics ----
#pragma unroll
        for (int mi = 0; mi < 2; mi++) {
            int r0 = wr + mi * 16 + g;
            int cR0 = cidx[r0], cR1 = cidx[r0 + 8];
            float s0 = 0.f, s1 = 0.f;
#pragma unroll
            for (int ni = 0; ni < 8; ni++) {
                int col0 = wc + ni * 8 + 2 * t;
                float bb0 = smf[B1_OFF + col0], bb1 = smf[B1_OFF + col0 + 1];
                float w00 = smf[W2_OFF + col0 * 17 + cR0];
                float w01 = smf[W2_OFF + (col0 + 1) * 17 + cR0];
                float w10 = smf[W2_OFF + col0 * 17 + cR1];
                float w11 = smf[W2_OFF + (col0 + 1) * 17 + cR1];
                s0 += fmaxf(acc[mi][ni][0] + bb0, 0.f) * w00
                    + fmaxf(acc[mi][ni][1] + bb1, 0.f) * w01;
                s1 += fmaxf(acc[mi][ni][2] + bb0, 0.f) * w10
                    + fmaxf(acc[mi][ni][3] + bb1, 0.f) * w11;
            }
            s0 += __shfl_xor_sync(0xffffffffu, s0, 1);
            s0 += __shfl_xor_sync(0xffffffffu, s0, 2);
            s1 += __shfl_xor_sync(0xffffffffu, s1, 1);
            s1 += __shfl_xor_sync(0xffffffffu, s1, 2);
            if (t == 0) {
                if (wn == 0) { s0 += smf[B2_OFF + cR0]; s1 += smf[B2_OFF + cR1]; }
                atomicAdd(&outp[row0 + r0], s0);
                atomicAdd(&outp[row0 + r0 + 8], s1);
            }
        }
        // no trailing sync: cidx next written after half0 sync of tile tt+1
    }
}

// ---------------------------------------------------------------------------
extern "C" void kernel_launch(void* const* d_in, const int* in_sizes, int n_in,
                              void* d_out, int out_size)
{
    const float* state = (const float*)d_in[0];
    const float* acs   = (const float*)d_in[1];
    const float* encW  = (const float*)d_in[2];
    const float* encb  = (const float*)d_in[3];
    const float* eW1   = (const float*)d_in[4];
    const float* eb1   = (const float*)d_in[5];
    const float* eW2   = (const float*)d_in[6];
    const float* eb2   = (const float*)d_in[7];
    const float* iW1   = (const float*)d_in[8];
    const float* ib1   = (const float*)d_in[9];
    const float* iW2   = (const float*)d_in[10];
    const float* ib2   = (const float*)d_in[11];
    float* out = (float*)d_out;

    const int B = in_sizes[0] / S_;          // 32768

    cudaFuncSetAttribute(enc_kernel,
        cudaFuncAttributeMaxDynamicSharedMemorySize, E_SMEMB);
    cudaFuncSetAttribute(critic_kernel,
        cudaFuncAttributeMaxDynamicSharedMemorySize, K_SMEMB);

    enc_kernel<<<B / 64 / NTE, 256, E_SMEMB>>>(state, encW, encb, acs, out, B);

    critic_kernel<<<NCTA, 256, K_SMEMB>>>(acs, eW1, eb1, eW2, eb2,
                                          ib1 - 0 + 0 == ib1 ? iW1 : iW1, ib1,
                                          iW2, ib2, out, B);
}